// round 2
// baseline (speedup 1.0000x reference)
#include <cuda_runtime.h>
#include <cstddef>

#define P_TOTAL (16*64*64)   // 65536 pixels, NHWC (C fastest)

// ---------------------------------------------------------------------------
// Scratch (device globals; no cudaMalloc allowed)
// ---------------------------------------------------------------------------
__device__ float g_Veff[256*256];
__device__ float g_ceff[256];
__device__ float g_Y1[(size_t)P_TOTAL*256];
__device__ float g_Y2[(size_t)P_TOTAL*256];
__device__ float g_base[(size_t)P_TOTAL*64];
__device__ float g_D0[(size_t)P_TOTAL*64];
__device__ float g_D1[(size_t)P_TOTAL*64];
__device__ float g_Acc[(size_t)P_TOTAL*64];

// Packed dual fp32 FMA (Blackwell FFMA2) — exact fp32, 2x rate vs FFMA.
__device__ __forceinline__ void ffma2(unsigned long long &d,
                                      const unsigned long long a,
                                      const unsigned long long b) {
    asm("fma.rn.f32x2 %0, %1, %2, %0;" : "+l"(d) : "l"(a), "l"(b));
}
__device__ __forceinline__ float lane_lo(unsigned long long v) {
    return reinterpret_cast<const float2&>(v).x;
}
__device__ __forceinline__ float lane_hi(unsigned long long v) {
    return reinterpret_cast<const float2&>(v).y;
}

// ---------------------------------------------------------------------------
// Step1 composition:  Z_i = x @ V_i + c_i  (columns of Veff / entries of ceff)
// ---------------------------------------------------------------------------
__global__ void veff_kernel(const float* __restrict__ w1,
                            const float* __restrict__ b1,
                            float* __restrict__ V,
                            float* __restrict__ c,
                            int i)
{
    const int mEnd = i * 64;
    if (blockIdx.x == 16) {
        const int n = threadIdx.x;
        if (n < 64) {
            float s = b1[n];
            for (int m = 0; m < mEnd; m += 4) {
                float c0 = c[m+0], c1 = c[m+1], c2 = c[m+2], c3 = c[m+3];
                float w0 = w1[(m+0)*64+n], w4 = w1[(m+1)*64+n];
                float w8 = w1[(m+2)*64+n], wc = w1[(m+3)*64+n];
                s = fmaf(c0, w0, s); s = fmaf(c1, w4, s);
                s = fmaf(c2, w8, s); s = fmaf(c3, wc, s);
            }
            c[mEnd + n] = s;
        }
        return;
    }
    const int gid = blockIdx.x * 256 + threadIdx.x;   // 0..4095
    const int j  = gid >> 4;                          // 0..255
    const int n0 = (gid & 15) * 4;                    // 0..60
    float4 s = make_float4(0.f, 0.f, 0.f, 0.f);
    if (j >= mEnd) s = *reinterpret_cast<const float4*>(w1 + j*64 + n0);
    for (int m = 0; m < mEnd; m += 4) {
        float v0 = V[j*256 + m+0], v1 = V[j*256 + m+1];
        float v2 = V[j*256 + m+2], v3 = V[j*256 + m+3];
        float4 a0 = *reinterpret_cast<const float4*>(w1 + (m+0)*64 + n0);
        float4 a1 = *reinterpret_cast<const float4*>(w1 + (m+1)*64 + n0);
        float4 a2 = *reinterpret_cast<const float4*>(w1 + (m+2)*64 + n0);
        float4 a3 = *reinterpret_cast<const float4*>(w1 + (m+3)*64 + n0);
        s.x = fmaf(v0,a0.x,s.x); s.y = fmaf(v0,a0.y,s.y); s.z = fmaf(v0,a0.z,s.z); s.w = fmaf(v0,a0.w,s.w);
        s.x = fmaf(v1,a1.x,s.x); s.y = fmaf(v1,a1.y,s.y); s.z = fmaf(v1,a1.z,s.z); s.w = fmaf(v1,a1.w,s.w);
        s.x = fmaf(v2,a2.x,s.x); s.y = fmaf(v2,a2.y,s.y); s.z = fmaf(v2,a2.z,s.z); s.w = fmaf(v2,a2.w,s.w);
        s.x = fmaf(v3,a3.x,s.x); s.y = fmaf(v3,a3.y,s.y); s.z = fmaf(v3,a3.z,s.z); s.w = fmaf(v3,a3.w,s.w);
    }
    *reinterpret_cast<float4*>(V + j*256 + mEnd + n0) = s;
}

// ---------------------------------------------------------------------------
// Conv-as-GEMM with packed f32x2 FMAs.
// Block = 128 px (two image rows) x 64 out channels. 256 threads.
// Per-thread: 8 px (4 packed pairs) x 4 ch  -> 16 FFMA2 per k.
// Weights duplicated in smem so the b operand pair loads directly.
// EPI: 0 = +bias, relu, write out (stride 256)
//      1 = +bias, write base, Y2 block0, D = base - Y1blk0
//      2 = (+Acc), write Acc, z = base+Acc -> Y2 blk(j+1), D = z - Y1blk(j+1)
// ---------------------------------------------------------------------------
template<int TAPS, int CIN, int EPI>
__global__ void __launch_bounds__(256)
conv_gemm2(const float* __restrict__ in,
           const float* __restrict__ W,
           const float* __restrict__ bias,
           float* __restrict__ out,
           const float* __restrict__ basep,
           const float* __restrict__ Y1p,
           float* __restrict__ Y2p,
           float* __restrict__ Dout,
           int wNStride, int tapStride, int jblk, int accumPrev)
{
    const int pxBase = blockIdx.x * 128;        // block fully inside one image
    const int n0  = blockIdx.y * 64;
    const int tid = threadIdx.x;
    const int tx  = tid & 15;                   // ch quad
    const int ty  = tid >> 4;                   // px octet
    const int l_px = tid & 127;                 // input-loader pixel
    const int l_kq = tid >> 7;                  // input-loader k half (0/1)
    const int w_k  = tid >> 4;                  // weight-loader k row
    const int w_n4 = tid & 15;                  // weight-loader n quad

    __shared__ float sIn[16][128];              // [k][px]
    __shared__ float sWd[16][128];              // [k][2*n+h] duplicated pairs

    unsigned long long acc[4][4];
#pragma unroll
    for (int i = 0; i < 4; ++i)
#pragma unroll
        for (int j = 0; j < 4; ++j) acc[i][j] = 0ULL;

    const int y_l = ((pxBase & 4095) >> 6) + (l_px >> 6);
    const int x_l = l_px & 63;

#pragma unroll 1
    for (int t = 0; t < TAPS; ++t) {
        const int dy = (TAPS == 9) ? (t / 3 - 1) : 0;
        const int dx = (TAPS == 9) ? (t % 3 - 1) : 0;
        const bool valid = ((unsigned)(y_l + dy) < 64u) && ((unsigned)(x_l + dx) < 64u);
        const float* inP = in + (size_t)(pxBase + l_px + dy*64 + dx) * CIN + l_kq*8;
        const float* wT  = W + (size_t)t * tapStride + (size_t)w_k * wNStride + n0 + w_n4*4;

#pragma unroll 1
        for (int kc = 0; kc < CIN / 16; ++kc) {
            float4 v0 = make_float4(0.f,0.f,0.f,0.f);
            float4 v1 = make_float4(0.f,0.f,0.f,0.f);
            if (valid) {
                v0 = *reinterpret_cast<const float4*>(inP + kc*16);
                v1 = *reinterpret_cast<const float4*>(inP + kc*16 + 4);
            }
            sIn[l_kq*8+0][l_px] = v0.x; sIn[l_kq*8+1][l_px] = v0.y;
            sIn[l_kq*8+2][l_px] = v0.z; sIn[l_kq*8+3][l_px] = v0.w;
            sIn[l_kq*8+4][l_px] = v1.x; sIn[l_kq*8+5][l_px] = v1.y;
            sIn[l_kq*8+6][l_px] = v1.z; sIn[l_kq*8+7][l_px] = v1.w;

            const float4 w4 = *reinterpret_cast<const float4*>(wT + (size_t)kc*16*wNStride);
            *reinterpret_cast<float4*>(&sWd[w_k][w_n4*8])     = make_float4(w4.x, w4.x, w4.y, w4.y);
            *reinterpret_cast<float4*>(&sWd[w_k][w_n4*8 + 4]) = make_float4(w4.z, w4.z, w4.w, w4.w);
            __syncthreads();

#pragma unroll
            for (int kk = 0; kk < 16; ++kk) {
                const ulonglong2 aA = *reinterpret_cast<const ulonglong2*>(&sIn[kk][ty*8]);
                const ulonglong2 aB = *reinterpret_cast<const ulonglong2*>(&sIn[kk][ty*8 + 4]);
                const ulonglong2 bA = *reinterpret_cast<const ulonglong2*>(&sWd[kk][tx*8]);
                const ulonglong2 bB = *reinterpret_cast<const ulonglong2*>(&sWd[kk][tx*8 + 4]);
                ffma2(acc[0][0], aA.x, bA.x); ffma2(acc[0][1], aA.x, bA.y);
                ffma2(acc[0][2], aA.x, bB.x); ffma2(acc[0][3], aA.x, bB.y);
                ffma2(acc[1][0], aA.y, bA.x); ffma2(acc[1][1], aA.y, bA.y);
                ffma2(acc[1][2], aA.y, bB.x); ffma2(acc[1][3], aA.y, bB.y);
                ffma2(acc[2][0], aB.x, bA.x); ffma2(acc[2][1], aB.x, bA.y);
                ffma2(acc[2][2], aB.x, bB.x); ffma2(acc[2][3], aB.x, bB.y);
                ffma2(acc[3][0], aB.y, bA.x); ffma2(acc[3][1], aB.y, bA.y);
                ffma2(acc[3][2], aB.y, bB.x); ffma2(acc[3][3], aB.y, bB.y);
            }
            __syncthreads();
        }
    }

    // ---------------- epilogue ----------------
    const int c4 = n0 + tx*4;
    float4 bv = make_float4(0.f,0.f,0.f,0.f);
    if (EPI != 2) bv = *reinterpret_cast<const float4*>(bias + c4);

#pragma unroll
    for (int pp = 0; pp < 4; ++pp) {
#pragma unroll
        for (int h = 0; h < 2; ++h) {
            const size_t p = (size_t)pxBase + ty*8 + pp*2 + h;
            float4 r;
            r.x = h ? lane_hi(acc[pp][0]) : lane_lo(acc[pp][0]);
            r.y = h ? lane_hi(acc[pp][1]) : lane_lo(acc[pp][1]);
            r.z = h ? lane_hi(acc[pp][2]) : lane_lo(acc[pp][2]);
            r.w = h ? lane_hi(acc[pp][3]) : lane_lo(acc[pp][3]);

            if (EPI == 0) {
                r.x = fmaxf(r.x + bv.x, 0.f); r.y = fmaxf(r.y + bv.y, 0.f);
                r.z = fmaxf(r.z + bv.z, 0.f); r.w = fmaxf(r.w + bv.w, 0.f);
                *reinterpret_cast<float4*>(out + p*256 + c4) = r;
            } else if (EPI == 1) {
                r.x += bv.x; r.y += bv.y; r.z += bv.z; r.w += bv.w;
                *reinterpret_cast<float4*>(out + p*64 + c4) = r;   // base
                *reinterpret_cast<float4*>(Y2p + p*256 + c4) = r;  // Y2 block 0
                const float4 y = *reinterpret_cast<const float4*>(Y1p + p*256 + c4);
                float4 d;
                d.x = r.x - y.x; d.y = r.y - y.y; d.z = r.z - y.z; d.w = r.w - y.w;
                *reinterpret_cast<float4*>(Dout + p*64 + c4) = d;
            } else {
                if (accumPrev) {
                    const float4 a = *reinterpret_cast<const float4*>(out + p*64 + c4);
                    r.x += a.x; r.y += a.y; r.z += a.z; r.w += a.w;
                }
                *reinterpret_cast<float4*>(out + p*64 + c4) = r;   // Acc
                const float4 b = *reinterpret_cast<const float4*>(basep + p*64 + c4);
                float4 z;
                z.x = b.x + r.x; z.y = b.y + r.y; z.z = b.z + r.z; z.w = b.w + r.w;
                *reinterpret_cast<float4*>(Y2p + p*256 + (jblk+1)*64 + c4) = z;
                if (jblk < 2) {
                    const float4 y = *reinterpret_cast<const float4*>(Y1p + p*256 + (jblk+1)*64 + c4);
                    float4 d;
                    d.x = z.x - y.x; d.y = z.y - y.y; d.z = z.z - y.z; d.w = z.w - y.w;
                    *reinterpret_cast<float4*>(Dout + p*64 + c4) = d;
                }
            }
        }
    }
}

// ---------------------------------------------------------------------------
// Step3: per-pixel scalar recurrence (replaces 256 sequential 1x1 convs)
// ---------------------------------------------------------------------------
__global__ void __launch_bounds__(256)
step3_kernel(const float* __restrict__ Y2,
             const float* __restrict__ x,
             const float* __restrict__ w3,
             const float* __restrict__ b3,
             float* __restrict__ out)
{
    __shared__ float sA[32][257];
    __shared__ float sw[256];
    const int tid = threadIdx.x;
    const size_t pBase = (size_t)blockIdx.x * 32;
    sw[tid] = w3[tid];

#pragma unroll
    for (int it = 0; it < 8; ++it) {
        const int g = it * 256 + tid;
        const int px = g >> 6;
        const int c = (g & 63) * 4;
        const float4 v = *reinterpret_cast<const float4*>(Y2 + (pBase + px)*256 + c);
        sA[px][c + 0] = fmaxf(v.x, 0.f);
        sA[px][c + 1] = fmaxf(v.y, 0.f);
        sA[px][c + 2] = fmaxf(v.z, 0.f);
        sA[px][c + 3] = fmaxf(v.w, 0.f);
    }
    __syncthreads();

    if (tid < 32) {
        float dot = 0.f;
#pragma unroll 8
        for (int c = 0; c < 256; ++c) dot = fmaf(sA[tid][c], sw[c], dot);
        const float bb = b3[0];
#pragma unroll 1
        for (int i = 0; i < 256; ++i) {
            const float a = sA[tid][i];
            const float z = dot + bb;
            sA[tid][i] = z;
            dot = fmaf(z - a, sw[i], dot);
        }
    }
    __syncthreads();

#pragma unroll
    for (int it = 0; it < 8; ++it) {
        const int g = it * 256 + tid;
        const int px = g >> 6;
        const int c = (g & 63) * 4;
        const float4 xv = *reinterpret_cast<const float4*>(x + (pBase + px)*256 + c);
        float4 r;
        r.x = sA[px][c + 0] + xv.x;
        r.y = sA[px][c + 1] + xv.y;
        r.z = sA[px][c + 2] + xv.z;
        r.w = sA[px][c + 3] + xv.w;
        *reinterpret_cast<float4*>(out + (pBase + px)*256 + c) = r;
    }
}

// ---------------------------------------------------------------------------
// Launch
// ---------------------------------------------------------------------------
extern "C" void kernel_launch(void* const* d_in, const int* in_sizes, int n_in,
                              void* d_out, int out_size)
{
    const float* x  = (const float*)d_in[0];
    const float* w1 = (const float*)d_in[1];
    const float* b1 = (const float*)d_in[2];
    const float* w2 = (const float*)d_in[3];
    const float* b2 = (const float*)d_in[4];
    const float* w3 = (const float*)d_in[5];
    const float* b3 = (const float*)d_in[6];
    float* out = (float*)d_out;

    float *Veff, *ceff, *Y1, *Y2, *base, *D0, *D1, *Acc;
    cudaGetSymbolAddress((void**)&Veff, g_Veff);
    cudaGetSymbolAddress((void**)&ceff, g_ceff);
    cudaGetSymbolAddress((void**)&Y1,   g_Y1);
    cudaGetSymbolAddress((void**)&Y2,   g_Y2);
    cudaGetSymbolAddress((void**)&base, g_base);
    cudaGetSymbolAddress((void**)&D0,   g_D0);
    cudaGetSymbolAddress((void**)&D1,   g_D1);
    cudaGetSymbolAddress((void**)&Acc,  g_Acc);

    // Phase 0: compose step1 into one effective 256x256 matrix
    for (int i = 0; i < 4; ++i)
        veff_kernel<<<17, 256>>>(w1, b1, Veff, ceff, i);

    // Phase 1: Y1 = relu(x @ Veff + ceff)
    conv_gemm2<1, 256, 0><<<dim3(512, 4), 256>>>(
        x, Veff, ceff, Y1, nullptr, nullptr, nullptr, nullptr,
        /*wN*/256, /*tap*/0, 0, 0);

    // Phase 2 base: base = conv3x3(Y1, W2) + b2 ; also Y2 blk0, D0
    conv_gemm2<9, 256, 1><<<dim3(512, 1), 256>>>(
        Y1, w2, b2, base, nullptr, Y1, Y2, D0,
        /*wN*/64, /*tap*/256*64, 0, 0);

    // Corrections: Z_{j+1} = base + sum_{m<=j} conv3x3(D_m, W2_blk_m)
    for (int j = 0; j < 3; ++j) {
        const float* Din = (j % 2 == 0) ? D0 : D1;
        float*       Dn  = (j % 2 == 0) ? D1 : D0;
        conv_gemm2<9, 64, 2><<<dim3(512, 1), 256>>>(
            Din, w2 + (size_t)j*64*64, nullptr, Acc, base, Y1, Y2, Dn,
            /*wN*/64, /*tap*/256*64, j, (j > 0) ? 1 : 0);
    }

    // Phase 3: per-pixel recurrence + residual
    step3_kernel<<<2048, 256>>>(Y2, x, w3, b3, out);
}

// round 4
// speedup vs baseline: 3.4780x; 3.4780x over previous
#include <cuda_runtime.h>
#include <cuda_bf16.h>
#include <cstdint>
#include <cstddef>

#define PTOT (16*64*64)   // 65536 pixels, NHWC (C fastest)

// ---------------------------------------------------------------------------
// Device globals (no cudaMalloc allowed)
// ---------------------------------------------------------------------------
__device__ float g_Veff[256*256];
__device__ float g_ceff[256];
__device__ __nv_bfloat16 g_xhi[(size_t)PTOT*256];
__device__ __nv_bfloat16 g_xlo[(size_t)PTOT*256];
__device__ __nv_bfloat16 g_Y1hi[(size_t)PTOT*256];
__device__ __nv_bfloat16 g_Y1lo[(size_t)PTOT*256];
__device__ float g_Y2[(size_t)PTOT*256];
__device__ float g_base[(size_t)PTOT*64];
__device__ float g_Acc[(size_t)PTOT*64];
__device__ __nv_bfloat16 g_Dhi0[(size_t)PTOT*64];
__device__ __nv_bfloat16 g_Dlo0[(size_t)PTOT*64];
__device__ __nv_bfloat16 g_Dhi1[(size_t)PTOT*64];
__device__ __nv_bfloat16 g_Dlo1[(size_t)PTOT*64];
__device__ __nv_bfloat16 g_Bbuf[158*4096];   // pre-swizzled bf16 weight tiles

// ---------------------------------------------------------------------------
// PTX helpers (sm_80-compatible only; no tcgen05 — ptxas targets plain sm_103)
// ---------------------------------------------------------------------------
__device__ __forceinline__ uint32_t s2u(const void* p) {
    uint32_t a;
    asm("{ .reg .u64 t; cvta.to.shared.u64 t, %1; cvt.u32.u64 %0, t; }"
        : "=r"(a) : "l"(p));
    return a;
}
#define SW128(o) ((uint32_t)(o) ^ (((uint32_t)(o) >> 3) & 0x70u))

__device__ __forceinline__ void bsplit(float v, __nv_bfloat16 &h, __nv_bfloat16 &l) {
    h = __float2bfloat16(v);
    l = __float2bfloat16(v - __bfloat162float(h));
}

__device__ __forceinline__ void cpa16(uint32_t dst, const void* src, bool valid) {
    asm volatile("cp.async.ca.shared.global [%0], [%1], 16, %2;"
                 :: "r"(dst), "l"(src), "r"(valid ? 16 : 0) : "memory");
}
__device__ __forceinline__ void cpa_commit() {
    asm volatile("cp.async.commit_group;" ::: "memory");
}
template<int N> __device__ __forceinline__ void cpa_wait() {
    asm volatile("cp.async.wait_group %0;" :: "n"(N) : "memory");
}

__device__ __forceinline__ void ldsm4(uint32_t* r, uint32_t addr) {
    asm volatile("ldmatrix.sync.aligned.m8n8.x4.shared.b16 {%0,%1,%2,%3}, [%4];"
                 : "=r"(r[0]), "=r"(r[1]), "=r"(r[2]), "=r"(r[3]) : "r"(addr));
}
__device__ __forceinline__ void mma_bf16(float* c, const uint32_t* a, const uint32_t* b) {
    asm volatile(
        "mma.sync.aligned.m16n8k16.row.col.f32.bf16.bf16.f32 "
        "{%0,%1,%2,%3}, {%4,%5,%6,%7}, {%8,%9}, {%0,%1,%2,%3};"
        : "+f"(c[0]), "+f"(c[1]), "+f"(c[2]), "+f"(c[3])
        : "r"(a[0]), "r"(a[1]), "r"(a[2]), "r"(a[3]), "r"(b[0]), "r"(b[1]));
}

// ---------------------------------------------------------------------------
// Step1 composition (fp32, small):  Z_i = x @ V_i + c_i
// ---------------------------------------------------------------------------
__global__ void veff_kernel(const float* __restrict__ w1,
                            const float* __restrict__ b1, int i)
{
    const int mEnd = i * 64;
    if (blockIdx.x == 16) {
        const int n = threadIdx.x;
        if (n < 64) {
            float s = b1[n];
            for (int m = 0; m < mEnd; m += 4) {
                s = fmaf(g_ceff[m+0], w1[(m+0)*64+n], s);
                s = fmaf(g_ceff[m+1], w1[(m+1)*64+n], s);
                s = fmaf(g_ceff[m+2], w1[(m+2)*64+n], s);
                s = fmaf(g_ceff[m+3], w1[(m+3)*64+n], s);
            }
            g_ceff[mEnd + n] = s;
        }
        return;
    }
    const int gid = blockIdx.x * 256 + threadIdx.x;
    const int j  = gid >> 4;
    const int n0 = (gid & 15) * 4;
    float4 s0 = make_float4(0.f,0.f,0.f,0.f), s1 = s0, s2 = s0, s3 = s0;
    if (j >= mEnd) s0 = *reinterpret_cast<const float4*>(w1 + j*64 + n0);
    for (int m = 0; m < mEnd; m += 16) {
#pragma unroll
        for (int q = 0; q < 4; ++q) {
            float4* acc = (q==0)? &s0 : (q==1)? &s1 : (q==2)? &s2 : &s3;
            const int mm = m + q*4;
#pragma unroll
            for (int r = 0; r < 4; ++r) {
                const float v = g_Veff[j*256 + mm + r];
                const float4 a = *reinterpret_cast<const float4*>(w1 + (mm+r)*64 + n0);
                acc->x = fmaf(v, a.x, acc->x);
                acc->y = fmaf(v, a.y, acc->y);
                acc->z = fmaf(v, a.z, acc->z);
                acc->w = fmaf(v, a.w, acc->w);
            }
        }
    }
    float4 s;
    s.x = (s0.x + s1.x) + (s2.x + s3.x);
    s.y = (s0.y + s1.y) + (s2.y + s3.y);
    s.z = (s0.z + s1.z) + (s2.z + s3.z);
    s.w = (s0.w + s1.w) + (s2.w + s3.w);
    *reinterpret_cast<float4*>(g_Veff + j*256 + mEnd + n0) = s;
}

// ---------------------------------------------------------------------------
// Weight prep: transpose + bf16-split + pre-swizzle all B tiles into g_Bbuf.
// Tiles (8KB each, [64 n rows][64 k cols] bf16, SW128):
//   [0,32):   phase1, idx = split*16 + kc*4 + nt     (src Veff)
//   [32,104): phase2, idx = 32 + split*36 + t*4 + kc (src w2)
//   [104,158): corr,  idx = 104 + j*18 + split*9 + t (src w2 block j)
// ---------------------------------------------------------------------------
__global__ void wprep_kernel(const float* __restrict__ w2)
{
    const int b = blockIdx.x;
    const int tid = threadIdx.x;
    for (int it = 0; it < 16; ++it) {
        const int id = it * 256 + tid;          // 0..4095
        const int n = id >> 6, k = id & 63;
        float val; int split;
        if (b < 32) {
            split = b >> 4; const int rem = b & 15;
            const int kc = rem >> 2, nt = rem & 3;
            val = g_Veff[(kc*64 + k)*256 + nt*64 + n];
        } else if (b < 104) {
            const int e = b - 32; split = e / 36; const int r = e % 36;
            const int t = r >> 2, kc = r & 3;
            val = w2[(size_t)t*16384 + (size_t)(kc*64 + k)*64 + n];
        } else {
            const int e = b - 104; const int j = e / 18; const int r = e % 18;
            split = r / 9; const int t = r % 9;
            val = w2[(size_t)t*16384 + (size_t)(j*64 + k)*64 + n];
        }
        __nv_bfloat16 h, l; bsplit(val, h, l);
        *reinterpret_cast<__nv_bfloat16*>(
            reinterpret_cast<char*>(g_Bbuf) + (size_t)b*8192 + SW128(n*128 + k*2))
            = (split == 0) ? h : l;
    }
}

// ---------------------------------------------------------------------------
// x -> bf16 hi/lo split (once)
// ---------------------------------------------------------------------------
__global__ void xsplit_kernel(const float4* __restrict__ x)
{
    const size_t g = (size_t)blockIdx.x * 256 + threadIdx.x;   // float4 index
    const float4 v = x[g];
    __nv_bfloat16 h0,l0,h1,l1,h2,l2,h3,l3;
    bsplit(v.x,h0,l0); bsplit(v.y,h1,l1); bsplit(v.z,h2,l2); bsplit(v.w,h3,l3);
    __nv_bfloat162 a, b;
    a.x=h0; a.y=h1; b.x=h2; b.y=h3;
    *reinterpret_cast<__nv_bfloat162*>(&g_xhi[g*4])   = a;
    *reinterpret_cast<__nv_bfloat162*>(&g_xhi[g*4+2]) = b;
    a.x=l0; a.y=l1; b.x=l2; b.y=l3;
    *reinterpret_cast<__nv_bfloat162*>(&g_xlo[g*4])   = a;
    *reinterpret_cast<__nv_bfloat162*>(&g_xlo[g*4+2]) = b;
}

// ---------------------------------------------------------------------------
// HMMA conv-GEMM. CTA: 128 px x 64 out channels. 256 threads = 8 warps.
// Warp tile 32px x 32n; per warp 2 Mtiles x 4 Ntiles of m16n8k16.
// Split precision: acc += Ahi*Bhi + Ahi*Blo + Alo*Bhi  (3 HMMA per tile/kstep).
// K loop in 64-ch chunks (per tap), cp.async double-buffered.
// PHASE 1: Y1 = relu(x@Veff + ceff) -> bf16 split     (grid 512 x 4)
// PHASE 2: base = conv3x3(Y1,W2)+b2; Y2 blk0; D0      (grid 512)
// PHASE 3: corr j: Acc += conv3x3(Dj, W2blkj); Y2 blk j+1; D_{j+1}  (grid 512)
// ---------------------------------------------------------------------------
#define SMEM_BYTES 98304
__device__ __forceinline__ uint32_t offA(int buf, int split) {
    return (uint32_t)buf*49152u + (uint32_t)split*16384u;
}
__device__ __forceinline__ uint32_t offB(int buf, int split) {
    return (uint32_t)buf*49152u + 32768u + (uint32_t)split*8192u;
}

template<int PHASE, int CIN, int NC>
__global__ void __launch_bounds__(256)
mma_conv(const __nv_bfloat16* __restrict__ Ahi,
         const __nv_bfloat16* __restrict__ Alo,
         const float* __restrict__ bias,
         __nv_bfloat16* __restrict__ DhiOut,
         __nv_bfloat16* __restrict__ DloOut,
         int jblk, int accumPrev)
{
    extern __shared__ char smem[];
    const uint32_t sb = s2u(smem);
    const int tid = threadIdx.x;
    const int lane = tid & 31;
    const int wid = tid >> 5;
    const int pxBase = blockIdx.x * 128;
    const int nt0 = (PHASE == 1) ? blockIdx.y : 0;
    const int n0 = nt0 * 64;
    const int y0 = (pxBase >> 6) & 63;

    const int wpx = (wid >> 1) * 32;       // warp px offset (0/32/64/96)
    const int wn  = (wid & 1) * 32;        // warp n offset (0/32)

    float c[2][4][4];
#pragma unroll
    for (int mt = 0; mt < 2; ++mt)
#pragma unroll
        for (int nt = 0; nt < 4; ++nt)
#pragma unroll
            for (int e = 0; e < 4; ++e) c[mt][nt][e] = 0.f;

    // ---- chunk staging ----
    auto stage = [&](int cidx, int buf) {
        int t, kcoff, tileH, tileL;
        if (PHASE == 1)      { t = 0;         kcoff = cidx * 64;       tileH = cidx*4 + nt0;            tileL = 16 + cidx*4 + nt0; }
        else if (PHASE == 2) { t = cidx >> 2; kcoff = (cidx & 3) * 64; tileH = 32 + cidx;               tileL = 68 + cidx; }
        else                 { t = cidx;      kcoff = 0;               tileH = 104 + jblk*18 + cidx;    tileL = 104 + jblk*18 + 9 + cidx; }
        const int dy = (PHASE == 1) ? 0 : (t / 3 - 1);
        const int dx = (PHASE == 1) ? 0 : (t % 3 - 1);

        const __nv_bfloat16* bsH = g_Bbuf + (size_t)tileH * 4096;
        const __nv_bfloat16* bsL = g_Bbuf + (size_t)tileL * 4096;
#pragma unroll
        for (int it = 0; it < 2; ++it) {
            const int id = it * 256 + tid;           // 0..511 (16B units)
            cpa16(sb + offB(buf,0) + id*16, bsH + id*8, true);
            cpa16(sb + offB(buf,1) + id*16, bsL + id*8, true);
        }
#pragma unroll
        for (int it = 0; it < 4; ++it) {
            const int id = it * 256 + tid;           // 0..1023
            const int r = id >> 3, u = id & 7;
            const int yy = y0 + (r >> 6) + dy;
            const int xx = (r & 63) + dx;
            const bool valid = ((unsigned)yy < 64u) && ((unsigned)xx < 64u);
            const long off = valid
                ? ((long)(pxBase + r + dy*64 + dx) * CIN + kcoff + u*8) : 0L;
            const uint32_t dsw = SW128(r*128 + u*16);
            cpa16(sb + offA(buf,0) + dsw, Ahi + off, valid);
            cpa16(sb + offA(buf,1) + dsw, Alo + off, valid);
        }
        cpa_commit();
    };

    stage(0, 0);
#pragma unroll 1
    for (int cc = 0; cc < NC; ++cc) {
        if (cc + 1 < NC) { stage(cc + 1, (cc + 1) & 1); cpa_wait<1>(); }
        else             { cpa_wait<0>(); }
        __syncthreads();

        const int buf = cc & 1;
        const uint32_t aHi = sb + offA(buf,0), aLo = sb + offA(buf,1);
        const uint32_t bHi = sb + offB(buf,0), bLo = sb + offB(buf,1);

#pragma unroll
        for (int ks = 0; ks < 4; ++ks) {
            uint32_t ah[2][4], al[2][4], bh[4][2], bl[4][2];
            {
                const int arow = wpx + ((lane >> 3) & 1) * 8 + (lane & 7);
                const int ak   = ks * 16 + (lane >> 4) * 8;
#pragma unroll
                for (int mt = 0; mt < 2; ++mt) {
                    const uint32_t asw = SW128((arow + mt*16) * 128 + ak * 2);
                    ldsm4(ah[mt], aHi + asw);
                    ldsm4(al[mt], aLo + asw);
                }
            }
            {
                const int m = lane >> 3, r = lane & 7;
#pragma unroll
                for (int np = 0; np < 2; ++np) {
                    const int brow = wn + np*16 + (m >> 1) * 8 + r;
                    const int bk   = ks * 16 + (m & 1) * 8;
                    const uint32_t bsw = SW128(brow * 128 + bk * 2);
                    uint32_t rg[4];
                    ldsm4(rg, bHi + bsw);
                    bh[np*2+0][0] = rg[0]; bh[np*2+0][1] = rg[1];
                    bh[np*2+1][0] = rg[2]; bh[np*2+1][1] = rg[3];
                    ldsm4(rg, bLo + bsw);
                    bl[np*2+0][0] = rg[0]; bl[np*2+0][1] = rg[1];
                    bl[np*2+1][0] = rg[2]; bl[np*2+1][1] = rg[3];
                }
            }
#pragma unroll
            for (int mt = 0; mt < 2; ++mt)
#pragma unroll
                for (int nt = 0; nt < 4; ++nt) {
                    mma_bf16(c[mt][nt], ah[mt], bh[nt]);
                    mma_bf16(c[mt][nt], ah[mt], bl[nt]);
                    mma_bf16(c[mt][nt], al[mt], bh[nt]);
                }
        }
        __syncthreads();
    }

    // ---- epilogue ----
    const int g = lane >> 2, tq = lane & 3;
#pragma unroll
    for (int mt = 0; mt < 2; ++mt) {
#pragma unroll
        for (int rh = 0; rh < 2; ++rh) {
            const size_t px = (size_t)pxBase + wpx + mt*16 + rh*8 + g;
#pragma unroll
            for (int nt = 0; nt < 4; ++nt) {
                const int ch = wn + nt*8 + tq*2;             // 0..63, even
                const float v0 = c[mt][nt][rh*2 + 0];
                const float v1 = c[mt][nt][rh*2 + 1];

                if (PHASE == 1) {
                    const float r0 = fmaxf(v0 + bias[n0+ch],   0.f);
                    const float r1 = fmaxf(v1 + bias[n0+ch+1], 0.f);
                    __nv_bfloat16 h0,l0,h1,l1; bsplit(r0,h0,l0); bsplit(r1,h1,l1);
                    __nv_bfloat162 hh, ll; hh.x=h0; hh.y=h1; ll.x=l0; ll.y=l1;
                    *reinterpret_cast<__nv_bfloat162*>(&g_Y1hi[px*256 + n0 + ch]) = hh;
                    *reinterpret_cast<__nv_bfloat162*>(&g_Y1lo[px*256 + n0 + ch]) = ll;
                } else if (PHASE == 2) {
                    const float r0 = v0 + bias[ch];
                    const float r1 = v1 + bias[ch+1];
                    float2 rr; rr.x = r0; rr.y = r1;
                    *reinterpret_cast<float2*>(&g_base[px*64 + ch]) = rr;
                    *reinterpret_cast<float2*>(&g_Y2[px*256 + ch])  = rr;
                    const __nv_bfloat162 yh = *reinterpret_cast<const __nv_bfloat162*>(&g_Y1hi[px*256 + ch]);
                    const __nv_bfloat162 yl = *reinterpret_cast<const __nv_bfloat162*>(&g_Y1lo[px*256 + ch]);
                    const float dd0 = r0 - (__bfloat162float(yh.x) + __bfloat162float(yl.x));
                    const float dd1 = r1 - (__bfloat162float(yh.y) + __bfloat162float(yl.y));
                    __nv_bfloat16 h0,l0,h1,l1; bsplit(dd0,h0,l0); bsplit(dd1,h1,l1);
                    __nv_bfloat162 hh, ll; hh.x=h0; hh.y=h1; ll.x=l0; ll.y=l1;
                    *reinterpret_cast<__nv_bfloat162*>(&DhiOut[px*64 + ch]) = hh;
                    *reinterpret_cast<__nv_bfloat162*>(&DloOut[px*64 + ch]) = ll;
                } else {
                    float r0 = v0, r1 = v1;
                    if (accumPrev) {
                        const float2 a = *reinterpret_cast<const float2*>(&g_Acc[px*64 + ch]);
                        r0 += a.x; r1 += a.y;
                    }
                    float2 rr; rr.x = r0; rr.y = r1;
                    *reinterpret_cast<float2*>(&g_Acc[px*64 + ch]) = rr;
                    const float2 b = *reinterpret_cast<const float2*>(&g_base[px*64 + ch]);
                    const float z0 = b.x + r0, z1 = b.y + r1;
                    float2 zz; zz.x = z0; zz.y = z1;
                    *reinterpret_cast<float2*>(&g_Y2[px*256 + (jblk+1)*64 + ch]) = zz;
                    if (jblk < 2) {
                        const __nv_bfloat162 yh = *reinterpret_cast<const __nv_bfloat162*>(&g_Y1hi[px*256 + (jblk+1)*64 + ch]);
                        const __nv_bfloat162 yl = *reinterpret_cast<const __nv_bfloat162*>(&g_Y1lo[px*256 + (jblk+1)*64 + ch]);
                        const float dd0 = z0 - (__bfloat162float(yh.x) + __bfloat162float(yl.x));
                        const float dd1 = z1 - (__bfloat162float(yh.y) + __bfloat162float(yl.y));
                        __nv_bfloat16 h0,l0,h1,l1; bsplit(dd0,h0,l0); bsplit(dd1,h1,l1);
                        __nv_bfloat162 hh, ll; hh.x=h0; hh.y=h1; ll.x=l0; ll.y=l1;
                        *reinterpret_cast<__nv_bfloat162*>(&DhiOut[px*64 + ch]) = hh;
                        *reinterpret_cast<__nv_bfloat162*>(&DloOut[px*64 + ch]) = ll;
                    }
                }
            }
        }
    }
}

// ---------------------------------------------------------------------------
// Step3: per-pixel scalar recurrence (replaces 256 sequential 1x1 convs)
// ---------------------------------------------------------------------------
__global__ void __launch_bounds__(256)
step3_kernel(const float* __restrict__ x,
             const float* __restrict__ w3,
             const float* __restrict__ b3,
             float* __restrict__ out)
{
    __shared__ float sA[32][257];
    __shared__ float sw[256];
    const int tid = threadIdx.x;
    const size_t pBase = (size_t)blockIdx.x * 32;
    sw[tid] = w3[tid];

#pragma unroll
    for (int it = 0; it < 8; ++it) {
        const int g = it * 256 + tid;
        const int px = g >> 6;
        const int c = (g & 63) * 4;
        const float4 v = *reinterpret_cast<const float4*>(g_Y2 + (pBase + px)*256 + c);
        sA[px][c + 0] = fmaxf(v.x, 0.f);
        sA[px][c + 1] = fmaxf(v.y, 0.f);
        sA[px][c + 2] = fmaxf(v.z, 0.f);
        sA[px][c + 3] = fmaxf(v.w, 0.f);
    }
    __syncthreads();

    if (tid < 32) {
        float dot = 0.f;
#pragma unroll 8
        for (int c = 0; c < 256; ++c) dot = fmaf(sA[tid][c], sw[c], dot);
        const float bb = b3[0];
#pragma unroll 1
        for (int i = 0; i < 256; ++i) {
            const float a = sA[tid][i];
            const float z = dot + bb;
            sA[tid][i] = z;
            dot = fmaf(z - a, sw[i], dot);
        }
    }
    __syncthreads();

#pragma unroll
    for (int it = 0; it < 8; ++it) {
        const int g = it * 256 + tid;
        const int px = g >> 6;
        const int c = (g & 63) * 4;
        const float4 xv = *reinterpret_cast<const float4*>(x + (pBase + px)*256 + c);
        float4 r;
        r.x = sA[px][c + 0] + xv.x;
        r.y = sA[px][c + 1] + xv.y;
        r.z = sA[px][c + 2] + xv.z;
        r.w = sA[px][c + 3] + xv.w;
        *reinterpret_cast<float4*>(out + (pBase + px)*256 + c) = r;
    }
}

// ---------------------------------------------------------------------------
// Launch
// ---------------------------------------------------------------------------
extern "C" void kernel_launch(void* const* d_in, const int* in_sizes, int n_in,
                              void* d_out, int out_size)
{
    const float* x  = (const float*)d_in[0];
    const float* w1 = (const float*)d_in[1];
    const float* b1 = (const float*)d_in[2];
    const float* w2 = (const float*)d_in[3];
    const float* b2 = (const float*)d_in[4];
    const float* w3 = (const float*)d_in[5];
    const float* b3 = (const float*)d_in[6];
    float* out = (float*)d_out;

    __nv_bfloat16 *xhi, *xlo, *Y1hi, *Y1lo, *Dhi0, *Dlo0, *Dhi1, *Dlo1;
    float *ceff;
    cudaGetSymbolAddress((void**)&xhi,  g_xhi);
    cudaGetSymbolAddress((void**)&xlo,  g_xlo);
    cudaGetSymbolAddress((void**)&Y1hi, g_Y1hi);
    cudaGetSymbolAddress((void**)&Y1lo, g_Y1lo);
    cudaGetSymbolAddress((void**)&Dhi0, g_Dhi0);
    cudaGetSymbolAddress((void**)&Dlo0, g_Dlo0);
    cudaGetSymbolAddress((void**)&Dhi1, g_Dhi1);
    cudaGetSymbolAddress((void**)&Dlo1, g_Dlo1);
    cudaGetSymbolAddress((void**)&ceff, g_ceff);

    cudaFuncSetAttribute(mma_conv<1,256,4>,
                         cudaFuncAttributeMaxDynamicSharedMemorySize, SMEM_BYTES);
    cudaFuncSetAttribute(mma_conv<2,256,36>,
                         cudaFuncAttributeMaxDynamicSharedMemorySize, SMEM_BYTES);
    cudaFuncSetAttribute(mma_conv<3,64,9>,
                         cudaFuncAttributeMaxDynamicSharedMemorySize, SMEM_BYTES);

    // Phase 0: compose step1 weights; prep B tiles; split x
    for (int i = 0; i < 4; ++i)
        veff_kernel<<<17, 256>>>(w1, b1, i);
    wprep_kernel<<<158, 256>>>(w2);
    xsplit_kernel<<<16384, 256>>>((const float4*)x);

    // Phase 1: Y1 = relu(x @ Veff + ceff)
    mma_conv<1,256,4><<<dim3(512, 4), 256, SMEM_BYTES>>>(
        xhi, xlo, ceff, nullptr, nullptr, 0, 0);

    // Phase 2: base = conv3x3(Y1, W2) + b2; Y2 blk0; D0
    mma_conv<2,256,36><<<512, 256, SMEM_BYTES>>>(
        Y1hi, Y1lo, b2, Dhi0, Dlo0, 0, 0);

    // Corrections: Z_{j+1} = base + sum_{m<=j} conv3x3(D_m, W2_blk_m)
    for (int j = 0; j < 3; ++j) {
        const __nv_bfloat16* Ah = (j & 1) ? Dhi1 : Dhi0;
        const __nv_bfloat16* Al = (j & 1) ? Dlo1 : Dlo0;
        __nv_bfloat16* Dh = (j & 1) ? Dhi0 : Dhi1;
        __nv_bfloat16* Dl = (j & 1) ? Dlo0 : Dlo1;
        mma_conv<3,64,9><<<512, 256, SMEM_BYTES>>>(
            Ah, Al, nullptr, Dh, Dl, j, (j > 0) ? 1 : 0);
    }

    // Phase 3: per-pixel recurrence + residual
    step3_kernel<<<2048, 256>>>(x, w3, b3, out);
}

// round 5
// speedup vs baseline: 3.6003x; 1.0352x over previous
#include <cuda_runtime.h>
#include <cuda_bf16.h>
#include <cstdint>
#include <cstddef>

#define PTOT (16*64*64)   // 65536 pixels, NHWC (C fastest)

// ---------------------------------------------------------------------------
// Device globals (no cudaMalloc allowed)
// ---------------------------------------------------------------------------
__device__ float g_Veff[256*256];
__device__ float g_ceff[256];
__device__ __nv_bfloat16 g_xhi[(size_t)PTOT*256];
__device__ __nv_bfloat16 g_xlo[(size_t)PTOT*256];
__device__ __nv_bfloat16 g_Y1hi[(size_t)PTOT*256];
__device__ __nv_bfloat16 g_Y1lo[(size_t)PTOT*256];
__device__ float g_Y2[(size_t)PTOT*256];
__device__ float g_base[(size_t)PTOT*64];
__device__ float g_Acc[(size_t)PTOT*64];
__device__ __nv_bfloat16 g_Dhi0[(size_t)PTOT*64];
__device__ __nv_bfloat16 g_Dlo0[(size_t)PTOT*64];
__device__ __nv_bfloat16 g_Dhi1[(size_t)PTOT*64];
__device__ __nv_bfloat16 g_Dlo1[(size_t)PTOT*64];
__device__ __nv_bfloat16 g_Bbuf[158*4096];   // pre-swizzled bf16 weight tiles

// ---------------------------------------------------------------------------
// PTX helpers (sm_80-compatible only; ptxas here targets plain sm_103)
// ---------------------------------------------------------------------------
__device__ __forceinline__ uint32_t s2u(const void* p) {
    uint32_t a;
    asm("{ .reg .u64 t; cvta.to.shared.u64 t, %1; cvt.u32.u64 %0, t; }"
        : "=r"(a) : "l"(p));
    return a;
}
#define SW128(o) ((uint32_t)(o) ^ (((uint32_t)(o) >> 3) & 0x70u))

__device__ __forceinline__ void bsplit(float v, __nv_bfloat16 &h, __nv_bfloat16 &l) {
    h = __float2bfloat16(v);
    l = __float2bfloat16(v - __bfloat162float(h));
}

__device__ __forceinline__ void cpa16(uint32_t dst, const void* src, bool valid) {
    asm volatile("cp.async.ca.shared.global [%0], [%1], 16, %2;"
                 :: "r"(dst), "l"(src), "r"(valid ? 16 : 0) : "memory");
}
__device__ __forceinline__ void cpa_commit() {
    asm volatile("cp.async.commit_group;" ::: "memory");
}
template<int N> __device__ __forceinline__ void cpa_wait() {
    asm volatile("cp.async.wait_group %0;" :: "n"(N) : "memory");
}

__device__ __forceinline__ void ldsm4(uint32_t* r, uint32_t addr) {
    asm volatile("ldmatrix.sync.aligned.m8n8.x4.shared.b16 {%0,%1,%2,%3}, [%4];"
                 : "=r"(r[0]), "=r"(r[1]), "=r"(r[2]), "=r"(r[3]) : "r"(addr));
}
__device__ __forceinline__ void mma_bf16(float* c, const uint32_t* a, const uint32_t* b) {
    asm volatile(
        "mma.sync.aligned.m16n8k16.row.col.f32.bf16.bf16.f32 "
        "{%0,%1,%2,%3}, {%4,%5,%6,%7}, {%8,%9}, {%0,%1,%2,%3};"
        : "+f"(c[0]), "+f"(c[1]), "+f"(c[2]), "+f"(c[3])
        : "r"(a[0]), "r"(a[1]), "r"(a[2]), "r"(a[3]), "r"(b[0]), "r"(b[1]));
}

// ---------------------------------------------------------------------------
// Step1 composition (fp32, small):  Z_i = x @ V_i + c_i
// ---------------------------------------------------------------------------
__global__ void veff_kernel(const float* __restrict__ w1,
                            const float* __restrict__ b1, int i)
{
    const int mEnd = i * 64;
    if (blockIdx.x == 16) {
        const int n = threadIdx.x;
        if (n < 64) {
            float s = b1[n];
            for (int m = 0; m < mEnd; m += 4) {
                s = fmaf(g_ceff[m+0], w1[(m+0)*64+n], s);
                s = fmaf(g_ceff[m+1], w1[(m+1)*64+n], s);
                s = fmaf(g_ceff[m+2], w1[(m+2)*64+n], s);
                s = fmaf(g_ceff[m+3], w1[(m+3)*64+n], s);
            }
            g_ceff[mEnd + n] = s;
        }
        return;
    }
    const int gid = blockIdx.x * 256 + threadIdx.x;
    const int j  = gid >> 4;
    const int n0 = (gid & 15) * 4;
    float4 s0 = make_float4(0.f,0.f,0.f,0.f), s1 = s0, s2 = s0, s3 = s0;
    if (j >= mEnd) s0 = *reinterpret_cast<const float4*>(w1 + j*64 + n0);
    for (int m = 0; m < mEnd; m += 16) {
#pragma unroll
        for (int q = 0; q < 4; ++q) {
            float4* acc = (q==0)? &s0 : (q==1)? &s1 : (q==2)? &s2 : &s3;
            const int mm = m + q*4;
#pragma unroll
            for (int r = 0; r < 4; ++r) {
                const float v = g_Veff[j*256 + mm + r];
                const float4 a = *reinterpret_cast<const float4*>(w1 + (mm+r)*64 + n0);
                acc->x = fmaf(v, a.x, acc->x);
                acc->y = fmaf(v, a.y, acc->y);
                acc->z = fmaf(v, a.z, acc->z);
                acc->w = fmaf(v, a.w, acc->w);
            }
        }
    }
    float4 s;
    s.x = (s0.x + s1.x) + (s2.x + s3.x);
    s.y = (s0.y + s1.y) + (s2.y + s3.y);
    s.z = (s0.z + s1.z) + (s2.z + s3.z);
    s.w = (s0.w + s1.w) + (s2.w + s3.w);
    *reinterpret_cast<float4*>(g_Veff + j*256 + mEnd + n0) = s;
}

// ---------------------------------------------------------------------------
// Weight prep: transpose + bf16-split + pre-swizzle all B tiles into g_Bbuf.
// Tiles (8KB each, [64 n rows][64 k cols] bf16, SW128):
//   [0,32):   phase1, idx = split*16 + kc*4 + nt     (src Veff)
//   [32,104): phase2, idx = 32 + split*36 + t*4 + kc (src w2)
//   [104,158): corr,  idx = 104 + j*18 + split*9 + t (src w2 block j)
// ---------------------------------------------------------------------------
__global__ void wprep_kernel(const float* __restrict__ w2)
{
    const int b = blockIdx.x;
    const int tid = threadIdx.x;
    for (int it = 0; it < 16; ++it) {
        const int id = it * 256 + tid;          // 0..4095
        const int n = id >> 6, k = id & 63;
        float val; int split;
        if (b < 32) {
            split = b >> 4; const int rem = b & 15;
            const int kc = rem >> 2, nt = rem & 3;
            val = g_Veff[(kc*64 + k)*256 + nt*64 + n];
        } else if (b < 104) {
            const int e = b - 32; split = e / 36; const int r = e % 36;
            const int t = r >> 2, kc = r & 3;
            val = w2[(size_t)t*16384 + (size_t)(kc*64 + k)*64 + n];
        } else {
            const int e = b - 104; const int j = e / 18; const int r = e % 18;
            split = r / 9; const int t = r % 9;
            val = w2[(size_t)t*16384 + (size_t)(j*64 + k)*64 + n];
        }
        __nv_bfloat16 h, l; bsplit(val, h, l);
        *reinterpret_cast<__nv_bfloat16*>(
            reinterpret_cast<char*>(g_Bbuf) + (size_t)b*8192 + SW128(n*128 + k*2))
            = (split == 0) ? h : l;
    }
}

// ---------------------------------------------------------------------------
// x -> bf16 hi/lo split (once)
// ---------------------------------------------------------------------------
__global__ void xsplit_kernel(const float4* __restrict__ x)
{
    const size_t g = (size_t)blockIdx.x * 256 + threadIdx.x;   // float4 index
    const float4 v = x[g];
    __nv_bfloat16 h0,l0,h1,l1,h2,l2,h3,l3;
    bsplit(v.x,h0,l0); bsplit(v.y,h1,l1); bsplit(v.z,h2,l2); bsplit(v.w,h3,l3);
    __nv_bfloat162 a, b;
    a.x=h0; a.y=h1; b.x=h2; b.y=h3;
    *reinterpret_cast<__nv_bfloat162*>(&g_xhi[g*4])   = a;
    *reinterpret_cast<__nv_bfloat162*>(&g_xhi[g*4+2]) = b;
    a.x=l0; a.y=l1; b.x=l2; b.y=l3;
    *reinterpret_cast<__nv_bfloat162*>(&g_xlo[g*4])   = a;
    *reinterpret_cast<__nv_bfloat162*>(&g_xlo[g*4+2]) = b;
}

// ===========================================================================
// PHASE 1: Y1 = relu(x @ Veff + ceff)   (1x1 conv, K=256, grid 512 x 4)
// CTA 128 px x 64 n, 8 warps, warp tile 32px x 32n, bf16 3-term split HMMA.
// ===========================================================================
#define SMEM1 98304
__device__ __forceinline__ uint32_t o1A(int buf, int split) {
    return (uint32_t)buf*49152u + (uint32_t)split*16384u;
}
__device__ __forceinline__ uint32_t o1B(int buf, int split) {
    return (uint32_t)buf*49152u + 32768u + (uint32_t)split*8192u;
}

__global__ void __launch_bounds__(256)
mma_p1(const __nv_bfloat16* __restrict__ Ahi,
       const __nv_bfloat16* __restrict__ Alo,
       const float* __restrict__ bias)
{
    extern __shared__ char smem[];
    const uint32_t sb = s2u(smem);
    const int tid = threadIdx.x;
    const int lane = tid & 31;
    const int wid = tid >> 5;
    const int pxBase = blockIdx.x * 128;
    const int nt0 = blockIdx.y;
    const int n0 = nt0 * 64;
    const int wpx = (wid >> 1) * 32;
    const int wn  = (wid & 1) * 32;

    float c[2][4][4];
#pragma unroll
    for (int mt = 0; mt < 2; ++mt)
#pragma unroll
        for (int nt = 0; nt < 4; ++nt)
#pragma unroll
            for (int e = 0; e < 4; ++e) c[mt][nt][e] = 0.f;

    auto stage = [&](int cidx, int buf) {
        const __nv_bfloat16* bsH = g_Bbuf + (size_t)(cidx*4 + nt0) * 4096;
        const __nv_bfloat16* bsL = g_Bbuf + (size_t)(16 + cidx*4 + nt0) * 4096;
#pragma unroll
        for (int it = 0; it < 2; ++it) {
            const int id = it * 256 + tid;
            cpa16(sb + o1B(buf,0) + id*16, bsH + id*8, true);
            cpa16(sb + o1B(buf,1) + id*16, bsL + id*8, true);
        }
#pragma unroll
        for (int it = 0; it < 4; ++it) {
            const int id = it * 256 + tid;
            const int r = id >> 3, u = id & 7;
            const long off = (long)(pxBase + r) * 256 + cidx*64 + u*8;
            const uint32_t dsw = SW128(r*128 + u*16);
            cpa16(sb + o1A(buf,0) + dsw, Ahi + off, true);
            cpa16(sb + o1A(buf,1) + dsw, Alo + off, true);
        }
        cpa_commit();
    };

    stage(0, 0);
#pragma unroll 1
    for (int cc = 0; cc < 4; ++cc) {
        if (cc + 1 < 4) { stage(cc + 1, (cc + 1) & 1); cpa_wait<1>(); }
        else            { cpa_wait<0>(); }
        __syncthreads();

        const int buf = cc & 1;
        const uint32_t aHi = sb + o1A(buf,0), aLo = sb + o1A(buf,1);
        const uint32_t bHi = sb + o1B(buf,0), bLo = sb + o1B(buf,1);

#pragma unroll
        for (int ks = 0; ks < 4; ++ks) {
            uint32_t ah[2][4], al[2][4], bh[4][2], bl[4][2];
            {
                const int arow = wpx + ((lane >> 3) & 1) * 8 + (lane & 7);
                const int ak   = ks * 16 + (lane >> 4) * 8;
#pragma unroll
                for (int mt = 0; mt < 2; ++mt) {
                    const uint32_t asw = SW128((arow + mt*16) * 128 + ak * 2);
                    ldsm4(ah[mt], aHi + asw);
                    ldsm4(al[mt], aLo + asw);
                }
            }
            {
                const int m = lane >> 3, r = lane & 7;
#pragma unroll
                for (int np = 0; np < 2; ++np) {
                    const int brow = wn + np*16 + (m >> 1) * 8 + r;
                    const int bk   = ks * 16 + (m & 1) * 8;
                    const uint32_t bsw = SW128(brow * 128 + bk * 2);
                    uint32_t rg[4];
                    ldsm4(rg, bHi + bsw);
                    bh[np*2+0][0] = rg[0]; bh[np*2+0][1] = rg[1];
                    bh[np*2+1][0] = rg[2]; bh[np*2+1][1] = rg[3];
                    ldsm4(rg, bLo + bsw);
                    bl[np*2+0][0] = rg[0]; bl[np*2+0][1] = rg[1];
                    bl[np*2+1][0] = rg[2]; bl[np*2+1][1] = rg[3];
                }
            }
#pragma unroll
            for (int mt = 0; mt < 2; ++mt)
#pragma unroll
                for (int nt = 0; nt < 4; ++nt) {
                    mma_bf16(c[mt][nt], ah[mt], bh[nt]);
                    mma_bf16(c[mt][nt], ah[mt], bl[nt]);
                    mma_bf16(c[mt][nt], al[mt], bh[nt]);
                }
        }
        __syncthreads();
    }

    const int g = lane >> 2, tq = lane & 3;
#pragma unroll
    for (int mt = 0; mt < 2; ++mt)
#pragma unroll
        for (int rh = 0; rh < 2; ++rh) {
            const size_t px = (size_t)pxBase + wpx + mt*16 + rh*8 + g;
#pragma unroll
            for (int nt = 0; nt < 4; ++nt) {
                const int ch = wn + nt*8 + tq*2;
                const float r0 = fmaxf(c[mt][nt][rh*2+0] + bias[n0+ch],   0.f);
                const float r1 = fmaxf(c[mt][nt][rh*2+1] + bias[n0+ch+1], 0.f);
                __nv_bfloat16 h0,l0,h1,l1; bsplit(r0,h0,l0); bsplit(r1,h1,l1);
                __nv_bfloat162 hh, ll; hh.x=h0; hh.y=h1; ll.x=l0; ll.y=l1;
                *reinterpret_cast<__nv_bfloat162*>(&g_Y1hi[px*256 + n0 + ch]) = hh;
                *reinterpret_cast<__nv_bfloat162*>(&g_Y1lo[px*256 + n0 + ch]) = ll;
            }
        }
}

// ===========================================================================
// 3x3 conv phases with HALO staging.
// A staged ONCE per 64-ch chunk as a 4-row x 66-px zero-padded halo tile
// (264 px x 128B per split); the 9 taps read shifted windows via per-lane
// ldmatrix row addresses. B (64x64 per tap) double-buffered via cp.async.
// PHASE 2 (NKC=4): base = conv3x3(Y1,W2)+b2; writes base, Y2 blk0, D0.
// PHASE 3 (NKC=1): Acc (+)= conv3x3(Dj, W2blkj); writes Acc, Y2 blk j+1, D.
// smem: Ahi [0,33792) Alo [33792,67584) B [67584 + buf*16384 + split*8192)
// ===========================================================================
#define SMEM3 100352
#define A3LO 33792u
__device__ __forceinline__ uint32_t o3B(int buf, int split) {
    return 67584u + (uint32_t)buf*16384u + (uint32_t)split*8192u;
}

template<int PHASE, int CIN, int NKC>
__global__ void __launch_bounds__(256)
mma_p3(const __nv_bfloat16* __restrict__ Ahi,
       const __nv_bfloat16* __restrict__ Alo,
       const float* __restrict__ bias,
       __nv_bfloat16* __restrict__ DhiOut,
       __nv_bfloat16* __restrict__ DloOut,
       int jblk, int accumPrev)
{
    extern __shared__ char smem[];
    const uint32_t sb = s2u(smem);
    const int tid = threadIdx.x;
    const int lane = tid & 31;
    const int wid = tid >> 5;
    const int pxBase = blockIdx.x * 128;
    const int y0 = (pxBase >> 6) & 63;
    const int img = pxBase >> 12;
    const int wpx = (wid >> 1) * 32;
    const int wn  = (wid & 1) * 32;

    float c[2][4][4];
#pragma unroll
    for (int mt = 0; mt < 2; ++mt)
#pragma unroll
        for (int nt = 0; nt < 4; ++nt)
#pragma unroll
            for (int e = 0; e < 4; ++e) c[mt][nt][e] = 0.f;

    // stage A halo tile for channel chunk kc (264 px x 8 x 16B x 2 splits)
    auto stageA = [&](int kc) {
#pragma unroll 1
        for (int it = 0; it < 9; ++it) {
            const int id = it * 256 + tid;           // 0..2303
            if (id < 2112) {
                const int r = id >> 3, u = id & 7;   // r: halo px 0..263
                const int row = r / 66;
                const int xt  = r - row * 66;
                const int y = y0 - 1 + row;
                const int x = xt - 1;
                const bool valid = ((unsigned)y < 64u) && ((unsigned)x < 64u);
                const long off = valid
                    ? ((long)(img*4096 + y*64 + x) * CIN + kc*64 + u*8) : 0L;
                const uint32_t dsw = SW128(r*128 + u*16);
                cpa16(sb + dsw, Ahi + off, valid);
                cpa16(sb + A3LO + dsw, Alo + off, valid);
            }
        }
    };

    auto stageB = [&](int kc, int t, int buf) {
        int tileH, tileL;
        if (PHASE == 2) { tileH = 32 + t*4 + kc;       tileL = 68 + t*4 + kc; }
        else            { tileH = 104 + jblk*18 + t;   tileL = 104 + jblk*18 + 9 + t; }
        const __nv_bfloat16* bsH = g_Bbuf + (size_t)tileH * 4096;
        const __nv_bfloat16* bsL = g_Bbuf + (size_t)tileL * 4096;
#pragma unroll
        for (int it = 0; it < 2; ++it) {
            const int id = it * 256 + tid;
            cpa16(sb + o3B(buf,0) + id*16, bsH + id*8, true);
            cpa16(sb + o3B(buf,1) + id*16, bsL + id*8, true);
        }
    };

#pragma unroll 1
    for (int kc = 0; kc < NKC; ++kc) {
        stageA(kc);
        stageB(kc, 0, 0);
        cpa_commit();
#pragma unroll 1
        for (int t = 0; t < 9; ++t) {
            if (t < 8) { stageB(kc, t + 1, (t + 1) & 1); cpa_commit(); cpa_wait<1>(); }
            else       { cpa_wait<0>(); }
            __syncthreads();

            const int dy = t / 3 - 1;
            const int dx = t % 3 - 1;
            const int buf = t & 1;
            const uint32_t bHi = sb + o3B(buf,0), bLo = sb + o3B(buf,1);

#pragma unroll
            for (int ks = 0; ks < 4; ++ks) {
                uint32_t ah[2][4], al[2][4], bh[4][2], bl[4][2];
                {
                    const int arow = wpx + ((lane >> 3) & 1) * 8 + (lane & 7);
                    const int ak   = ks * 16 + (lane >> 4) * 8;
#pragma unroll
                    for (int mt = 0; mt < 2; ++mt) {
                        const int ar = arow + mt*16;
                        const int tpx = ((ar >> 6) + dy + 1) * 66 + (ar & 63) + dx + 1;
                        const uint32_t asw = SW128(tpx * 128 + ak * 2);
                        ldsm4(ah[mt], sb + asw);
                        ldsm4(al[mt], sb + A3LO + asw);
                    }
                }
                {
                    const int m = lane >> 3, r = lane & 7;
#pragma unroll
                    for (int np = 0; np < 2; ++np) {
                        const int brow = wn + np*16 + (m >> 1) * 8 + r;
                        const int bk   = ks * 16 + (m & 1) * 8;
                        const uint32_t bsw = SW128(brow * 128 + bk * 2);
                        uint32_t rg[4];
                        ldsm4(rg, bHi + bsw);
                        bh[np*2+0][0] = rg[0]; bh[np*2+0][1] = rg[1];
                        bh[np*2+1][0] = rg[2]; bh[np*2+1][1] = rg[3];
                        ldsm4(rg, bLo + bsw);
                        bl[np*2+0][0] = rg[0]; bl[np*2+0][1] = rg[1];
                        bl[np*2+1][0] = rg[2]; bl[np*2+1][1] = rg[3];
                    }
                }
#pragma unroll
                for (int mt = 0; mt < 2; ++mt)
#pragma unroll
                    for (int nt = 0; nt < 4; ++nt) {
                        mma_bf16(c[mt][nt], ah[mt], bh[nt]);
                        mma_bf16(c[mt][nt], ah[mt], bl[nt]);
                        mma_bf16(c[mt][nt], al[mt], bh[nt]);
                    }
            }
            __syncthreads();
        }
    }

    // ---- epilogue ----
    const int g = lane >> 2, tq = lane & 3;
#pragma unroll
    for (int mt = 0; mt < 2; ++mt) {
#pragma unroll
        for (int rh = 0; rh < 2; ++rh) {
            const size_t px = (size_t)pxBase + wpx + mt*16 + rh*8 + g;
#pragma unroll
            for (int nt = 0; nt < 4; ++nt) {
                const int ch = wn + nt*8 + tq*2;
                const float v0 = c[mt][nt][rh*2 + 0];
                const float v1 = c[mt][nt][rh*2 + 1];

                if (PHASE == 2) {
                    const float r0 = v0 + bias[ch];
                    const float r1 = v1 + bias[ch+1];
                    float2 rr; rr.x = r0; rr.y = r1;
                    *reinterpret_cast<float2*>(&g_base[px*64 + ch]) = rr;
                    *reinterpret_cast<float2*>(&g_Y2[px*256 + ch])  = rr;
                    const __nv_bfloat162 yh = *reinterpret_cast<const __nv_bfloat162*>(&g_Y1hi[px*256 + ch]);
                    const __nv_bfloat162 yl = *reinterpret_cast<const __nv_bfloat162*>(&g_Y1lo[px*256 + ch]);
                    const float dd0 = r0 - (__bfloat162float(yh.x) + __bfloat162float(yl.x));
                    const float dd1 = r1 - (__bfloat162float(yh.y) + __bfloat162float(yl.y));
                    __nv_bfloat16 h0,l0,h1,l1; bsplit(dd0,h0,l0); bsplit(dd1,h1,l1);
                    __nv_bfloat162 hh, ll; hh.x=h0; hh.y=h1; ll.x=l0; ll.y=l1;
                    *reinterpret_cast<__nv_bfloat162*>(&DhiOut[px*64 + ch]) = hh;
                    *reinterpret_cast<__nv_bfloat162*>(&DloOut[px*64 + ch]) = ll;
                } else {
                    float r0 = v0, r1 = v1;
                    if (accumPrev) {
                        const float2 a = *reinterpret_cast<const float2*>(&g_Acc[px*64 + ch]);
                        r0 += a.x; r1 += a.y;
                    }
                    float2 rr; rr.x = r0; rr.y = r1;
                    *reinterpret_cast<float2*>(&g_Acc[px*64 + ch]) = rr;
                    const float2 b = *reinterpret_cast<const float2*>(&g_base[px*64 + ch]);
                    const float z0 = b.x + r0, z1 = b.y + r1;
                    float2 zz; zz.x = z0; zz.y = z1;
                    *reinterpret_cast<float2*>(&g_Y2[px*256 + (jblk+1)*64 + ch]) = zz;
                    if (jblk < 2) {
                        const __nv_bfloat162 yh = *reinterpret_cast<const __nv_bfloat162*>(&g_Y1hi[px*256 + (jblk+1)*64 + ch]);
                        const __nv_bfloat162 yl = *reinterpret_cast<const __nv_bfloat162*>(&g_Y1lo[px*256 + (jblk+1)*64 + ch]);
                        const float dd0 = z0 - (__bfloat162float(yh.x) + __bfloat162float(yl.x));
                        const float dd1 = z1 - (__bfloat162float(yh.y) + __bfloat162float(yl.y));
                        __nv_bfloat16 h0,l0,h1,l1; bsplit(dd0,h0,l0); bsplit(dd1,h1,l1);
                        __nv_bfloat162 hh, ll; hh.x=h0; hh.y=h1; ll.x=l0; ll.y=l1;
                        *reinterpret_cast<__nv_bfloat162*>(&DhiOut[px*64 + ch]) = hh;
                        *reinterpret_cast<__nv_bfloat162*>(&DloOut[px*64 + ch]) = ll;
                    }
                }
            }
        }
    }
}

// ---------------------------------------------------------------------------
// Step3: per-pixel scalar recurrence (replaces 256 sequential 1x1 convs)
// ---------------------------------------------------------------------------
__global__ void __launch_bounds__(256)
step3_kernel(const float* __restrict__ x,
             const float* __restrict__ w3,
             const float* __restrict__ b3,
             float* __restrict__ out)
{
    __shared__ float sA[32][257];
    __shared__ float sw[256];
    const int tid = threadIdx.x;
    const size_t pBase = (size_t)blockIdx.x * 32;
    sw[tid] = w3[tid];

#pragma unroll
    for (int it = 0; it < 8; ++it) {
        const int g = it * 256 + tid;
        const int px = g >> 6;
        const int c = (g & 63) * 4;
        const float4 v = *reinterpret_cast<const float4*>(g_Y2 + (pBase + px)*256 + c);
        sA[px][c + 0] = fmaxf(v.x, 0.f);
        sA[px][c + 1] = fmaxf(v.y, 0.f);
        sA[px][c + 2] = fmaxf(v.z, 0.f);
        sA[px][c + 3] = fmaxf(v.w, 0.f);
    }
    __syncthreads();

    if (tid < 32) {
        float dot = 0.f;
#pragma unroll 8
        for (int c = 0; c < 256; ++c) dot = fmaf(sA[tid][c], sw[c], dot);
        const float bb = b3[0];
#pragma unroll 1
        for (int i = 0; i < 256; ++i) {
            const float a = sA[tid][i];
            const float z = dot + bb;
            sA[tid][i] = z;
            dot = fmaf(z - a, sw[i], dot);
        }
    }
    __syncthreads();

#pragma unroll
    for (int it = 0; it < 8; ++it) {
        const int g = it * 256 + tid;
        const int px = g >> 6;
        const int c = (g & 63) * 4;
        const float4 xv = *reinterpret_cast<const float4*>(x + (pBase + px)*256 + c);
        float4 r;
        r.x = sA[px][c + 0] + xv.x;
        r.y = sA[px][c + 1] + xv.y;
        r.z = sA[px][c + 2] + xv.z;
        r.w = sA[px][c + 3] + xv.w;
        *reinterpret_cast<float4*>(out + (pBase + px)*256 + c) = r;
    }
}

// ---------------------------------------------------------------------------
// Launch
// ---------------------------------------------------------------------------
extern "C" void kernel_launch(void* const* d_in, const int* in_sizes, int n_in,
                              void* d_out, int out_size)
{
    const float* x  = (const float*)d_in[0];
    const float* w1 = (const float*)d_in[1];
    const float* b1 = (const float*)d_in[2];
    const float* w2 = (const float*)d_in[3];
    const float* b2 = (const float*)d_in[4];
    const float* w3 = (const float*)d_in[5];
    const float* b3 = (const float*)d_in[6];
    float* out = (float*)d_out;

    __nv_bfloat16 *xhi, *xlo, *Y1hi, *Y1lo, *Dhi0, *Dlo0, *Dhi1, *Dlo1;
    float *ceff;
    cudaGetSymbolAddress((void**)&xhi,  g_xhi);
    cudaGetSymbolAddress((void**)&xlo,  g_xlo);
    cudaGetSymbolAddress((void**)&Y1hi, g_Y1hi);
    cudaGetSymbolAddress((void**)&Y1lo, g_Y1lo);
    cudaGetSymbolAddress((void**)&Dhi0, g_Dhi0);
    cudaGetSymbolAddress((void**)&Dlo0, g_Dlo0);
    cudaGetSymbolAddress((void**)&Dhi1, g_Dhi1);
    cudaGetSymbolAddress((void**)&Dlo1, g_Dlo1);
    cudaGetSymbolAddress((void**)&ceff, g_ceff);

    cudaFuncSetAttribute(mma_p1,
                         cudaFuncAttributeMaxDynamicSharedMemorySize, SMEM1);
    cudaFuncSetAttribute(mma_p3<2,256,4>,
                         cudaFuncAttributeMaxDynamicSharedMemorySize, SMEM3);
    cudaFuncSetAttribute(mma_p3<3,64,1>,
                         cudaFuncAttributeMaxDynamicSharedMemorySize, SMEM3);

    // Phase 0: compose step1 weights; prep B tiles; split x
    for (int i = 0; i < 4; ++i)
        veff_kernel<<<17, 256>>>(w1, b1, i);
    wprep_kernel<<<158, 256>>>(w2);
    xsplit_kernel<<<16384, 256>>>((const float4*)x);

    // Phase 1: Y1 = relu(x @ Veff + ceff)
    mma_p1<<<dim3(512, 4), 256, SMEM1>>>(xhi, xlo, ceff);

    // Phase 2: base = conv3x3(Y1, W2) + b2; Y2 blk0; D0
    mma_p3<2,256,4><<<512, 256, SMEM3>>>(
        Y1hi, Y1lo, b2, Dhi0, Dlo0, 0, 0);

    // Corrections: Z_{j+1} = base + sum_{m<=j} conv3x3(D_m, W2_blk_m)
    for (int j = 0; j < 3; ++j) {
        const __nv_bfloat16* Ah = (j & 1) ? Dhi1 : Dhi0;
        const __nv_bfloat16* Al = (j & 1) ? Dlo1 : Dlo0;
        __nv_bfloat16* Dh = (j & 1) ? Dhi0 : Dhi1;
        __nv_bfloat16* Dl = (j & 1) ? Dlo0 : Dlo1;
        mma_p3<3,64,1><<<512, 256, SMEM3>>>(
            Ah, Al, nullptr, Dh, Dl, j, (j > 0) ? 1 : 0);
    }

    // Phase 3: per-pixel recurrence + residual
    step3_kernel<<<2048, 256>>>(x, w3, b3, out);
}

// round 6
// speedup vs baseline: 3.7598x; 1.0443x over previous
#include <cuda_runtime.h>
#include <cuda_bf16.h>
#include <cstdint>
#include <cstddef>

#define PTOT (16*64*64)   // 65536 pixels, NHWC (C fastest)

// ---------------------------------------------------------------------------
// Device globals (no cudaMalloc allowed)
// ---------------------------------------------------------------------------
__device__ float g_Veff[256*256];
__device__ float g_ceff[256];
__device__ __nv_bfloat16 g_xhi[(size_t)PTOT*256];
__device__ __nv_bfloat16 g_xlo[(size_t)PTOT*256];
__device__ __nv_bfloat16 g_Y1hi[(size_t)PTOT*256];
__device__ __nv_bfloat16 g_Y1lo[(size_t)PTOT*256];
__device__ float g_Y2[(size_t)PTOT*256];
__device__ float g_base[(size_t)PTOT*64];
__device__ float g_Acc[(size_t)PTOT*64];
__device__ __nv_bfloat16 g_Dhi0[(size_t)PTOT*64];
__device__ __nv_bfloat16 g_Dlo0[(size_t)PTOT*64];
__device__ __nv_bfloat16 g_Dhi1[(size_t)PTOT*64];
__device__ __nv_bfloat16 g_Dlo1[(size_t)PTOT*64];
__device__ __nv_bfloat16 g_Bbuf[158*4096];   // pre-swizzled bf16 weight tiles

// ---------------------------------------------------------------------------
// PTX helpers (sm_80-compatible only; ptxas here targets plain sm_103)
// ---------------------------------------------------------------------------
__device__ __forceinline__ uint32_t s2u(const void* p) {
    uint32_t a;
    asm("{ .reg .u64 t; cvta.to.shared.u64 t, %1; cvt.u32.u64 %0, t; }"
        : "=r"(a) : "l"(p));
    return a;
}
#define SW128(o) ((uint32_t)(o) ^ (((uint32_t)(o) >> 3) & 0x70u))

__device__ __forceinline__ void bsplit(float v, __nv_bfloat16 &h, __nv_bfloat16 &l) {
    h = __float2bfloat16(v);
    l = __float2bfloat16(v - __bfloat162float(h));
}

__device__ __forceinline__ void cpa16(uint32_t dst, const void* src, bool valid) {
    asm volatile("cp.async.ca.shared.global [%0], [%1], 16, %2;"
                 :: "r"(dst), "l"(src), "r"(valid ? 16 : 0) : "memory");
}
__device__ __forceinline__ void cpa_commit() {
    asm volatile("cp.async.commit_group;" ::: "memory");
}
template<int N> __device__ __forceinline__ void cpa_wait() {
    asm volatile("cp.async.wait_group %0;" :: "n"(N) : "memory");
}

__device__ __forceinline__ void ldsm4(uint32_t* r, uint32_t addr) {
    asm volatile("ldmatrix.sync.aligned.m8n8.x4.shared.b16 {%0,%1,%2,%3}, [%4];"
                 : "=r"(r[0]), "=r"(r[1]), "=r"(r[2]), "=r"(r[3]) : "r"(addr));
}
__device__ __forceinline__ void mma_bf16(float* c, const uint32_t* a, const uint32_t* b) {
    asm volatile(
        "mma.sync.aligned.m16n8k16.row.col.f32.bf16.bf16.f32 "
        "{%0,%1,%2,%3}, {%4,%5,%6,%7}, {%8,%9}, {%0,%1,%2,%3};"
        : "+f"(c[0]), "+f"(c[1]), "+f"(c[2]), "+f"(c[3])
        : "r"(a[0]), "r"(a[1]), "r"(a[2]), "r"(a[3]), "r"(b[0]), "r"(b[1]));
}

// ---------------------------------------------------------------------------
// Step1 composition in ONE kernel (replaces 4 serial veff launches).
// Row-independent recurrence: block i of row j uses only row j's earlier
// entries. One warp per row (row 256 = bias row). Row state: 8 regs/lane
// (m = lane + 32q). w1 transposed in smem; new entries via butterfly reduce.
// ---------------------------------------------------------------------------
#define COMPOSE_SMEM (64*256*4 + 64*4)
__global__ void __launch_bounds__(256)
compose_kernel(const float* __restrict__ w1, const float* __restrict__ b1)
{
    extern __shared__ float sh[];
    float* w1t = sh;                 // w1t[n*256 + m] = w1[m*64 + n]
    float* b1s = sh + 64*256;
    const int tid = threadIdx.x;
    const int lane = tid & 31;

#pragma unroll
    for (int it = 0; it < 64; ++it) {
        const int id = it * 256 + tid;       // 0..16383
        const int m = id >> 6, n = id & 63;
        w1t[n*256 + m] = w1[id];
    }
    if (tid < 64) b1s[tid] = b1[tid];
    __syncthreads();

    const int gw = blockIdx.x * 8 + (tid >> 5);   // 0..263
    if (gw > 256) return;
    const bool isC = (gw == 256);
    const int j = gw;

    float v[8], ex[2];
#pragma unroll
    for (int q = 0; q < 2; ++q)
        ex[q] = isC ? b1s[lane + 32*q] : w1[j*64 + lane + 32*q];
    v[0] = ex[0]; v[1] = ex[1];
    v[2]=v[3]=v[4]=v[5]=v[6]=v[7] = 0.f;

#pragma unroll
    for (int i = 1; i < 4; ++i) {
        const int mEnd = 64 * i;
        const bool addEx = isC || (j >= mEnd);
#pragma unroll 8
        for (int n = 0; n < 64; ++n) {
            float p = 0.f;
#pragma unroll
            for (int q = 0; q < 8; ++q)
                if (q < 2*i) p = fmaf(v[q], w1t[n*256 + lane + 32*q], p);
#pragma unroll
            for (int o = 16; o > 0; o >>= 1)
                p += __shfl_xor_sync(0xffffffffu, p, o);
            if (lane == (n & 31))
                v[2*i + (n >> 5)] = p + (addEx ? ex[n >> 5] : 0.f);
        }
    }

    if (isC) {
#pragma unroll
        for (int q = 0; q < 8; ++q) g_ceff[lane + 32*q] = v[q];
    } else {
#pragma unroll
        for (int q = 0; q < 8; ++q) g_Veff[j*256 + lane + 32*q] = v[q];
    }
}

// ---------------------------------------------------------------------------
// Weight prep: transpose + bf16-split + pre-swizzle all B tiles into g_Bbuf.
// Tiles (8KB each, [64 n rows][64 k cols] bf16, SW128):
//   [0,32):   phase1, idx = split*16 + kc*4 + nt     (src Veff)
//   [32,104): phase2, idx = 32 + split*36 + t*4 + kc (src w2)
//   [104,158): corr,  idx = 104 + j*18 + split*9 + t (src w2 block j)
// ---------------------------------------------------------------------------
__global__ void wprep_kernel(const float* __restrict__ w2)
{
    const int b = blockIdx.x;
    const int tid = threadIdx.x;
    for (int it = 0; it < 16; ++it) {
        const int id = it * 256 + tid;          // 0..4095
        const int n = id >> 6, k = id & 63;
        float val; int split;
        if (b < 32) {
            split = b >> 4; const int rem = b & 15;
            const int kc = rem >> 2, nt = rem & 3;
            val = g_Veff[(kc*64 + k)*256 + nt*64 + n];
        } else if (b < 104) {
            const int e = b - 32; split = e / 36; const int r = e % 36;
            const int t = r >> 2, kc = r & 3;
            val = w2[(size_t)t*16384 + (size_t)(kc*64 + k)*64 + n];
        } else {
            const int e = b - 104; const int j = e / 18; const int r = e % 18;
            split = r / 9; const int t = r % 9;
            val = w2[(size_t)t*16384 + (size_t)(j*64 + k)*64 + n];
        }
        __nv_bfloat16 h, l; bsplit(val, h, l);
        *reinterpret_cast<__nv_bfloat16*>(
            reinterpret_cast<char*>(g_Bbuf) + (size_t)b*8192 + SW128(n*128 + k*2))
            = (split == 0) ? h : l;
    }
}

// ---------------------------------------------------------------------------
// x -> bf16 hi/lo split (once)
// ---------------------------------------------------------------------------
__global__ void xsplit_kernel(const float4* __restrict__ x)
{
    const size_t g = (size_t)blockIdx.x * 256 + threadIdx.x;   // float4 index
    const float4 v = x[g];
    __nv_bfloat16 h0,l0,h1,l1,h2,l2,h3,l3;
    bsplit(v.x,h0,l0); bsplit(v.y,h1,l1); bsplit(v.z,h2,l2); bsplit(v.w,h3,l3);
    __nv_bfloat162 a, b;
    a.x=h0; a.y=h1; b.x=h2; b.y=h3;
    *reinterpret_cast<__nv_bfloat162*>(&g_xhi[g*4])   = a;
    *reinterpret_cast<__nv_bfloat162*>(&g_xhi[g*4+2]) = b;
    a.x=l0; a.y=l1; b.x=l2; b.y=l3;
    *reinterpret_cast<__nv_bfloat162*>(&g_xlo[g*4])   = a;
    *reinterpret_cast<__nv_bfloat162*>(&g_xlo[g*4+2]) = b;
}

// ===========================================================================
// PHASE 1: Y1 = relu(x @ Veff + ceff)   (1x1 conv, K=256, grid 512 x 4)
// CTA 128 px x 64 n, 8 warps, warp tile 32px x 32n, bf16 3-term split HMMA.
// ===========================================================================
#define SMEM1 98304
__device__ __forceinline__ uint32_t o1A(int buf, int split) {
    return (uint32_t)buf*49152u + (uint32_t)split*16384u;
}
__device__ __forceinline__ uint32_t o1B(int buf, int split) {
    return (uint32_t)buf*49152u + 32768u + (uint32_t)split*8192u;
}

__global__ void __launch_bounds__(256)
mma_p1(const __nv_bfloat16* __restrict__ Ahi,
       const __nv_bfloat16* __restrict__ Alo,
       const float* __restrict__ bias)
{
    extern __shared__ char smem[];
    const uint32_t sb = s2u(smem);
    const int tid = threadIdx.x;
    const int lane = tid & 31;
    const int wid = tid >> 5;
    const int pxBase = blockIdx.x * 128;
    const int nt0 = blockIdx.y;
    const int n0 = nt0 * 64;
    const int wpx = (wid >> 1) * 32;
    const int wn  = (wid & 1) * 32;

    float c[2][4][4];
#pragma unroll
    for (int mt = 0; mt < 2; ++mt)
#pragma unroll
        for (int nt = 0; nt < 4; ++nt)
#pragma unroll
            for (int e = 0; e < 4; ++e) c[mt][nt][e] = 0.f;

    auto stage = [&](int cidx, int buf) {
        const __nv_bfloat16* bsH = g_Bbuf + (size_t)(cidx*4 + nt0) * 4096;
        const __nv_bfloat16* bsL = g_Bbuf + (size_t)(16 + cidx*4 + nt0) * 4096;
#pragma unroll
        for (int it = 0; it < 2; ++it) {
            const int id = it * 256 + tid;
            cpa16(sb + o1B(buf,0) + id*16, bsH + id*8, true);
            cpa16(sb + o1B(buf,1) + id*16, bsL + id*8, true);
        }
#pragma unroll
        for (int it = 0; it < 4; ++it) {
            const int id = it * 256 + tid;
            const int r = id >> 3, u = id & 7;
            const long off = (long)(pxBase + r) * 256 + cidx*64 + u*8;
            const uint32_t dsw = SW128(r*128 + u*16);
            cpa16(sb + o1A(buf,0) + dsw, Ahi + off, true);
            cpa16(sb + o1A(buf,1) + dsw, Alo + off, true);
        }
        cpa_commit();
    };

    stage(0, 0);
#pragma unroll 1
    for (int cc = 0; cc < 4; ++cc) {
        if (cc + 1 < 4) { stage(cc + 1, (cc + 1) & 1); cpa_wait<1>(); }
        else            { cpa_wait<0>(); }
        __syncthreads();

        const int buf = cc & 1;
        const uint32_t aHi = sb + o1A(buf,0), aLo = sb + o1A(buf,1);
        const uint32_t bHi = sb + o1B(buf,0), bLo = sb + o1B(buf,1);

#pragma unroll
        for (int ks = 0; ks < 4; ++ks) {
            uint32_t ah[2][4], al[2][4], bh[4][2], bl[4][2];
            {
                const int arow = wpx + ((lane >> 3) & 1) * 8 + (lane & 7);
                const int ak   = ks * 16 + (lane >> 4) * 8;
#pragma unroll
                for (int mt = 0; mt < 2; ++mt) {
                    const uint32_t asw = SW128((arow + mt*16) * 128 + ak * 2);
                    ldsm4(ah[mt], aHi + asw);
                    ldsm4(al[mt], aLo + asw);
                }
            }
            {
                const int m = lane >> 3, r = lane & 7;
#pragma unroll
                for (int np = 0; np < 2; ++np) {
                    const int brow = wn + np*16 + (m >> 1) * 8 + r;
                    const int bk   = ks * 16 + (m & 1) * 8;
                    const uint32_t bsw = SW128(brow * 128 + bk * 2);
                    uint32_t rg[4];
                    ldsm4(rg, bHi + bsw);
                    bh[np*2+0][0] = rg[0]; bh[np*2+0][1] = rg[1];
                    bh[np*2+1][0] = rg[2]; bh[np*2+1][1] = rg[3];
                    ldsm4(rg, bLo + bsw);
                    bl[np*2+0][0] = rg[0]; bl[np*2+0][1] = rg[1];
                    bl[np*2+1][0] = rg[2]; bl[np*2+1][1] = rg[3];
                }
            }
#pragma unroll
            for (int mt = 0; mt < 2; ++mt)
#pragma unroll
                for (int nt = 0; nt < 4; ++nt) {
                    mma_bf16(c[mt][nt], ah[mt], bh[nt]);
                    mma_bf16(c[mt][nt], ah[mt], bl[nt]);
                    mma_bf16(c[mt][nt], al[mt], bh[nt]);
                }
        }
        __syncthreads();
    }

    const int g = lane >> 2, tq = lane & 3;
#pragma unroll
    for (int mt = 0; mt < 2; ++mt)
#pragma unroll
        for (int rh = 0; rh < 2; ++rh) {
            const size_t px = (size_t)pxBase + wpx + mt*16 + rh*8 + g;
#pragma unroll
            for (int nt = 0; nt < 4; ++nt) {
                const int ch = wn + nt*8 + tq*2;
                const float r0 = fmaxf(c[mt][nt][rh*2+0] + bias[n0+ch],   0.f);
                const float r1 = fmaxf(c[mt][nt][rh*2+1] + bias[n0+ch+1], 0.f);
                __nv_bfloat16 h0,l0,h1,l1; bsplit(r0,h0,l0); bsplit(r1,h1,l1);
                __nv_bfloat162 hh, ll; hh.x=h0; hh.y=h1; ll.x=l0; ll.y=l1;
                *reinterpret_cast<__nv_bfloat162*>(&g_Y1hi[px*256 + n0 + ch]) = hh;
                *reinterpret_cast<__nv_bfloat162*>(&g_Y1lo[px*256 + n0 + ch]) = ll;
            }
        }
}

// ===========================================================================
// 3x3 conv phases with HALO staging.
// A staged ONCE per 64-ch chunk as a 4-row x 66-px zero-padded halo tile
// (264 px x 128B per split); the 9 taps read shifted windows via per-lane
// ldmatrix row addresses. B (64x64 per tap) double-buffered via cp.async.
// PHASE 2 (NKC=4): base = conv3x3(Y1,W2)+b2; writes base, Y2 blk0, D0.
// PHASE 3 (NKC=1): Acc (+)= conv3x3(Dj, W2blkj); writes Acc, Y2 blk j+1, D.
// smem: Ahi [0,33792) Alo [33792,67584) B [67584 + buf*16384 + split*8192)
// ===========================================================================
#define SMEM3 100352
#define A3LO 33792u
__device__ __forceinline__ uint32_t o3B(int buf, int split) {
    return 67584u + (uint32_t)buf*16384u + (uint32_t)split*8192u;
}

template<int PHASE, int CIN, int NKC>
__global__ void __launch_bounds__(256)
mma_p3(const __nv_bfloat16* __restrict__ Ahi,
       const __nv_bfloat16* __restrict__ Alo,
       const float* __restrict__ bias,
       __nv_bfloat16* __restrict__ DhiOut,
       __nv_bfloat16* __restrict__ DloOut,
       int jblk, int accumPrev)
{
    extern __shared__ char smem[];
    const uint32_t sb = s2u(smem);
    const int tid = threadIdx.x;
    const int lane = tid & 31;
    const int wid = tid >> 5;
    const int pxBase = blockIdx.x * 128;
    const int y0 = (pxBase >> 6) & 63;
    const int img = pxBase >> 12;
    const int wpx = (wid >> 1) * 32;
    const int wn  = (wid & 1) * 32;

    float c[2][4][4];
#pragma unroll
    for (int mt = 0; mt < 2; ++mt)
#pragma unroll
        for (int nt = 0; nt < 4; ++nt)
#pragma unroll
            for (int e = 0; e < 4; ++e) c[mt][nt][e] = 0.f;

    // stage A halo tile for channel chunk kc (264 px x 8 x 16B x 2 splits)
    auto stageA = [&](int kc) {
#pragma unroll 1
        for (int it = 0; it < 9; ++it) {
            const int id = it * 256 + tid;           // 0..2303
            if (id < 2112) {
                const int r = id >> 3, u = id & 7;   // r: halo px 0..263
                const int row = r / 66;
                const int xt  = r - row * 66;
                const int y = y0 - 1 + row;
                const int x = xt - 1;
                const bool valid = ((unsigned)y < 64u) && ((unsigned)x < 64u);
                const long off = valid
                    ? ((long)(img*4096 + y*64 + x) * CIN + kc*64 + u*8) : 0L;
                const uint32_t dsw = SW128(r*128 + u*16);
                cpa16(sb + dsw, Ahi + off, valid);
                cpa16(sb + A3LO + dsw, Alo + off, valid);
            }
        }
    };

    auto stageB = [&](int kc, int t, int buf) {
        int tileH, tileL;
        if (PHASE == 2) { tileH = 32 + t*4 + kc;       tileL = 68 + t*4 + kc; }
        else            { tileH = 104 + jblk*18 + t;   tileL = 104 + jblk*18 + 9 + t; }
        const __nv_bfloat16* bsH = g_Bbuf + (size_t)tileH * 4096;
        const __nv_bfloat16* bsL = g_Bbuf + (size_t)tileL * 4096;
#pragma unroll
        for (int it = 0; it < 2; ++it) {
            const int id = it * 256 + tid;
            cpa16(sb + o3B(buf,0) + id*16, bsH + id*8, true);
            cpa16(sb + o3B(buf,1) + id*16, bsL + id*8, true);
        }
    };

#pragma unroll 1
    for (int kc = 0; kc < NKC; ++kc) {
        stageA(kc);
        stageB(kc, 0, 0);
        cpa_commit();
#pragma unroll 1
        for (int t = 0; t < 9; ++t) {
            if (t < 8) { stageB(kc, t + 1, (t + 1) & 1); cpa_commit(); cpa_wait<1>(); }
            else       { cpa_wait<0>(); }
            __syncthreads();

            const int dy = t / 3 - 1;
            const int dx = t % 3 - 1;
            const int buf = t & 1;
            const uint32_t bHi = sb + o3B(buf,0), bLo = sb + o3B(buf,1);

#pragma unroll
            for (int ks = 0; ks < 4; ++ks) {
                uint32_t ah[2][4], al[2][4], bh[4][2], bl[4][2];
                {
                    const int arow = wpx + ((lane >> 3) & 1) * 8 + (lane & 7);
                    const int ak   = ks * 16 + (lane >> 4) * 8;
#pragma unroll
                    for (int mt = 0; mt < 2; ++mt) {
                        const int ar = arow + mt*16;
                        const int tpx = ((ar >> 6) + dy + 1) * 66 + (ar & 63) + dx + 1;
                        const uint32_t asw = SW128(tpx * 128 + ak * 2);
                        ldsm4(ah[mt], sb + asw);
                        ldsm4(al[mt], sb + A3LO + asw);
                    }
                }
                {
                    const int m = lane >> 3, r = lane & 7;
#pragma unroll
                    for (int np = 0; np < 2; ++np) {
                        const int brow = wn + np*16 + (m >> 1) * 8 + r;
                        const int bk   = ks * 16 + (m & 1) * 8;
                        const uint32_t bsw = SW128(brow * 128 + bk * 2);
                        uint32_t rg[4];
                        ldsm4(rg, bHi + bsw);
                        bh[np*2+0][0] = rg[0]; bh[np*2+0][1] = rg[1];
                        bh[np*2+1][0] = rg[2]; bh[np*2+1][1] = rg[3];
                        ldsm4(rg, bLo + bsw);
                        bl[np*2+0][0] = rg[0]; bl[np*2+0][1] = rg[1];
                        bl[np*2+1][0] = rg[2]; bl[np*2+1][1] = rg[3];
                    }
                }
#pragma unroll
                for (int mt = 0; mt < 2; ++mt)
#pragma unroll
                    for (int nt = 0; nt < 4; ++nt) {
                        mma_bf16(c[mt][nt], ah[mt], bh[nt]);
                        mma_bf16(c[mt][nt], ah[mt], bl[nt]);
                        mma_bf16(c[mt][nt], al[mt], bh[nt]);
                    }
            }
            __syncthreads();
        }
    }

    // ---- epilogue ----
    const int g = lane >> 2, tq = lane & 3;
#pragma unroll
    for (int mt = 0; mt < 2; ++mt) {
#pragma unroll
        for (int rh = 0; rh < 2; ++rh) {
            const size_t px = (size_t)pxBase + wpx + mt*16 + rh*8 + g;
#pragma unroll
            for (int nt = 0; nt < 4; ++nt) {
                const int ch = wn + nt*8 + tq*2;
                const float v0 = c[mt][nt][rh*2 + 0];
                const float v1 = c[mt][nt][rh*2 + 1];

                if (PHASE == 2) {
                    const float r0 = v0 + bias[ch];
                    const float r1 = v1 + bias[ch+1];
                    float2 rr; rr.x = r0; rr.y = r1;
                    *reinterpret_cast<float2*>(&g_base[px*64 + ch]) = rr;
                    *reinterpret_cast<float2*>(&g_Y2[px*256 + ch])  = rr;
                    const __nv_bfloat162 yh = *reinterpret_cast<const __nv_bfloat162*>(&g_Y1hi[px*256 + ch]);
                    const __nv_bfloat162 yl = *reinterpret_cast<const __nv_bfloat162*>(&g_Y1lo[px*256 + ch]);
                    const float dd0 = r0 - (__bfloat162float(yh.x) + __bfloat162float(yl.x));
                    const float dd1 = r1 - (__bfloat162float(yh.y) + __bfloat162float(yl.y));
                    __nv_bfloat16 h0,l0,h1,l1; bsplit(dd0,h0,l0); bsplit(dd1,h1,l1);
                    __nv_bfloat162 hh, ll; hh.x=h0; hh.y=h1; ll.x=l0; ll.y=l1;
                    *reinterpret_cast<__nv_bfloat162*>(&DhiOut[px*64 + ch]) = hh;
                    *reinterpret_cast<__nv_bfloat162*>(&DloOut[px*64 + ch]) = ll;
                } else {
                    float r0 = v0, r1 = v1;
                    if (accumPrev) {
                        const float2 a = *reinterpret_cast<const float2*>(&g_Acc[px*64 + ch]);
                        r0 += a.x; r1 += a.y;
                    }
                    float2 rr; rr.x = r0; rr.y = r1;
                    *reinterpret_cast<float2*>(&g_Acc[px*64 + ch]) = rr;
                    const float2 b = *reinterpret_cast<const float2*>(&g_base[px*64 + ch]);
                    const float z0 = b.x + r0, z1 = b.y + r1;
                    float2 zz; zz.x = z0; zz.y = z1;
                    *reinterpret_cast<float2*>(&g_Y2[px*256 + (jblk+1)*64 + ch]) = zz;
                    if (jblk < 2) {
                        const __nv_bfloat162 yh = *reinterpret_cast<const __nv_bfloat162*>(&g_Y1hi[px*256 + (jblk+1)*64 + ch]);
                        const __nv_bfloat162 yl = *reinterpret_cast<const __nv_bfloat162*>(&g_Y1lo[px*256 + (jblk+1)*64 + ch]);
                        const float dd0 = z0 - (__bfloat162float(yh.x) + __bfloat162float(yl.x));
                        const float dd1 = z1 - (__bfloat162float(yh.y) + __bfloat162float(yl.y));
                        __nv_bfloat16 h0,l0,h1,l1; bsplit(dd0,h0,l0); bsplit(dd1,h1,l1);
                        __nv_bfloat162 hh, ll; hh.x=h0; hh.y=h1; ll.x=l0; ll.y=l1;
                        *reinterpret_cast<__nv_bfloat162*>(&DhiOut[px*64 + ch]) = hh;
                        *reinterpret_cast<__nv_bfloat162*>(&DloOut[px*64 + ch]) = ll;
                    }
                }
            }
        }
    }
}

// ---------------------------------------------------------------------------
// Step3: per-pixel scalar recurrence (replaces 256 sequential 1x1 convs)
// ---------------------------------------------------------------------------
__global__ void __launch_bounds__(256)
step3_kernel(const float* __restrict__ x,
             const float* __restrict__ w3,
             const float* __restrict__ b3,
             float* __restrict__ out)
{
    __shared__ float sA[32][257];
    __shared__ float sw[256];
    const int tid = threadIdx.x;
    const size_t pBase = (size_t)blockIdx.x * 32;
    sw[tid] = w3[tid];

#pragma unroll
    for (int it = 0; it < 8; ++it) {
        const int g = it * 256 + tid;
        const int px = g >> 6;
        const int c = (g & 63) * 4;
        const float4 v = *reinterpret_cast<const float4*>(g_Y2 + (pBase + px)*256 + c);
        sA[px][c + 0] = fmaxf(v.x, 0.f);
        sA[px][c + 1] = fmaxf(v.y, 0.f);
        sA[px][c + 2] = fmaxf(v.z, 0.f);
        sA[px][c + 3] = fmaxf(v.w, 0.f);
    }
    __syncthreads();

    if (tid < 32) {
        float dot = 0.f;
#pragma unroll 8
        for (int c = 0; c < 256; ++c) dot = fmaf(sA[tid][c], sw[c], dot);
        const float bb = b3[0];
#pragma unroll 1
        for (int i = 0; i < 256; ++i) {
            const float a = sA[tid][i];
            const float z = dot + bb;
            sA[tid][i] = z;
            dot = fmaf(z - a, sw[i], dot);
        }
    }
    __syncthreads();

#pragma unroll
    for (int it = 0; it < 8; ++it) {
        const int g = it * 256 + tid;
        const int px = g >> 6;
        const int c = (g & 63) * 4;
        const float4 xv = *reinterpret_cast<const float4*>(x + (pBase + px)*256 + c);
        float4 r;
        r.x = sA[px][c + 0] + xv.x;
        r.y = sA[px][c + 1] + xv.y;
        r.z = sA[px][c + 2] + xv.z;
        r.w = sA[px][c + 3] + xv.w;
        *reinterpret_cast<float4*>(out + (pBase + px)*256 + c) = r;
    }
}

// ---------------------------------------------------------------------------
// Launch
// ---------------------------------------------------------------------------
extern "C" void kernel_launch(void* const* d_in, const int* in_sizes, int n_in,
                              void* d_out, int out_size)
{
    const float* x  = (const float*)d_in[0];
    const float* w1 = (const float*)d_in[1];
    const float* b1 = (const float*)d_in[2];
    const float* w2 = (const float*)d_in[3];
    const float* b2 = (const float*)d_in[4];
    const float* w3 = (const float*)d_in[5];
    const float* b3 = (const float*)d_in[6];
    float* out = (float*)d_out;

    __nv_bfloat16 *xhi, *xlo, *Y1hi, *Y1lo, *Dhi0, *Dlo0, *Dhi1, *Dlo1;
    float *ceff;
    cudaGetSymbolAddress((void**)&xhi,  g_xhi);
    cudaGetSymbolAddress((void**)&xlo,  g_xlo);
    cudaGetSymbolAddress((void**)&Y1hi, g_Y1hi);
    cudaGetSymbolAddress((void**)&Y1lo, g_Y1lo);
    cudaGetSymbolAddress((void**)&Dhi0, g_Dhi0);
    cudaGetSymbolAddress((void**)&Dlo0, g_Dlo0);
    cudaGetSymbolAddress((void**)&Dhi1, g_Dhi1);
    cudaGetSymbolAddress((void**)&Dlo1, g_Dlo1);
    cudaGetSymbolAddress((void**)&ceff, g_ceff);

    cudaFuncSetAttribute(compose_kernel,
                         cudaFuncAttributeMaxDynamicSharedMemorySize, COMPOSE_SMEM);
    cudaFuncSetAttribute(mma_p1,
                         cudaFuncAttributeMaxDynamicSharedMemorySize, SMEM1);
    cudaFuncSetAttribute(mma_p3<2,256,4>,
                         cudaFuncAttributeMaxDynamicSharedMemorySize, SMEM3);
    cudaFuncSetAttribute(mma_p3<3,64,1>,
                         cudaFuncAttributeMaxDynamicSharedMemorySize, SMEM3);

    // Phase 0: compose step1 weights (ONE kernel); prep B tiles; split x
    compose_kernel<<<33, 256, COMPOSE_SMEM>>>(w1, b1);
    wprep_kernel<<<158, 256>>>(w2);
    xsplit_kernel<<<16384, 256>>>((const float4*)x);

    // Phase 1: Y1 = relu(x @ Veff + ceff)
    mma_p1<<<dim3(512, 4), 256, SMEM1>>>(xhi, xlo, ceff);

    // Phase 2: base = conv3x3(Y1, W2) + b2; Y2 blk0; D0
    mma_p3<2,256,4><<<512, 256, SMEM3>>>(
        Y1hi, Y1lo, b2, Dhi0, Dlo0, 0, 0);

    // Corrections: Z_{j+1} = base + sum_{m<=j} conv3x3(D_m, W2_blk_m)
    for (int j = 0; j < 3; ++j) {
        const __nv_bfloat16* Ah = (j & 1) ? Dhi1 : Dhi0;
        const __nv_bfloat16* Al = (j & 1) ? Dlo1 : Dlo0;
        __nv_bfloat16* Dh = (j & 1) ? Dhi0 : Dhi1;
        __nv_bfloat16* Dl = (j & 1) ? Dlo0 : Dlo1;
        mma_p3<3,64,1><<<512, 256, SMEM3>>>(
            Ah, Al, nullptr, Dh, Dl, j, (j > 0) ? 1 : 0);
    }

    // Phase 3: per-pixel recurrence + residual
    step3_kernel<<<2048, 256>>>(x, w3, b3, out);
}